// round 2
// baseline (speedup 1.0000x reference)
#include <cuda_runtime.h>
#include <math.h>

#define BB 256       // batch
#define TT 256       // timesteps
#define FF 511       // raw feature dim
#define UU 512       // units
#define ZZ 2048      // 4*U
#define KK 1024      // fused K = U (x) + U (h)
#define GRID 128     // persistent grid (<= SM count -> co-resident, barrier-safe)
#define THR 256

// ---------------- device scratch ----------------
__device__ float g_Xt[(size_t)TT * BB * UU];    // [t][b][u] input incl. score col
__device__ float g_enc[(size_t)BB * TT * UU];   // [b][t][u] encoder hidden states
__device__ float g_Wenc[(size_t)KK * ZZ];       // [Wx; Wh] stacked row-major [K][N]
__device__ float g_Wdec[(size_t)KK * ZZ];
__device__ float g_A[BB * KK];                  // GEMM operand: [x_t | h]
__device__ float g_Z[BB * ZZ];                  // pre-activations
__device__ float g_h[BB * UU];
__device__ float g_c[BB * UU];
__device__ float g_x0[BB * UU];                 // decoder initial input
__device__ unsigned g_cnt;                      // barrier arrive count
__device__ unsigned g_gen;                      // barrier generation

__device__ __forceinline__ float sigf(float x) { return 1.0f / (1.0f + expf(-x)); }

// ---------------- software grid barrier ----------------
__device__ __forceinline__ void gsync(unsigned target) {
    __syncthreads();
    if (threadIdx.x == 0) {
        __threadfence();
        unsigned t = atomicAdd(&g_cnt, 1u);
        if (t == GRID - 1u) {
            g_cnt = 0u;
            __threadfence();
            atomicExch(&g_gen, target);
        } else {
            while (atomicAdd(&g_gen, 0u) < target) __nanosleep(32);
            __threadfence();
        }
    }
    __syncthreads();
}

// ---------------- prep kernels ----------------
__global__ void prep_x_kernel(const float* __restrict__ inputs, const float* __restrict__ score) {
    size_t idx = (size_t)blockIdx.x * blockDim.x + threadIdx.x;
    if (idx >= (size_t)TT * BB * UU) return;
    int t = (int)(idx / (BB * UU));
    int rem = (int)(idx % (BB * UU));
    int b = rem / UU;
    int u = rem % UU;
    g_Xt[idx] = (u < FF) ? inputs[((size_t)b * TT + t) * FF + u] : score[b];
}

__global__ void mean_kernel() {
    int idx = blockIdx.x * blockDim.x + threadIdx.x;
    if (idx >= BB * UU) return;
    float s = 0.f;
    #pragma unroll 4
    for (int t = 0; t < TT; t++) s += g_Xt[(size_t)t * (BB * UU) + idx];
    g_x0[idx] = s * (1.0f / TT);
}

__global__ void prep_w_kernel(float* __restrict__ dst,
                              const float* __restrict__ Wx, const float* __restrict__ Wh) {
    size_t idx = (size_t)blockIdx.x * blockDim.x + threadIdx.x;
    if (idx >= (size_t)KK * ZZ) return;
    int k = (int)(idx / ZZ);
    int n = (int)(idx % ZZ);
    dst[idx] = (k < UU) ? Wx[(size_t)k * ZZ + n] : Wh[(size_t)(k - UU) * ZZ + n];
}

__global__ void init_kernel() {
    int idx = blockIdx.x * blockDim.x + threadIdx.x;   // over B*K
    if (idx == 0) { g_cnt = 0u; g_gen = 0u; }
    if (idx >= BB * KK) return;
    int b = idx / KK;
    int col = idx % KK;
    if (col < UU) {
        g_A[idx] = g_Xt[(size_t)b * UU + col];   // Xt[t=0][b][col]
    } else {
        g_A[idx] = 0.f;
        int u = col - UU;
        g_h[b * UU + u] = 0.f;
        g_c[b * UU + u] = 0.f;
    }
}

// ---------------- GEMM tile phase (per CTA: one 64x64 tile of Z) ----------------
__device__ __forceinline__ void gemm_tile(const float* __restrict__ W,
                                          const float* __restrict__ bias,
                                          float (&As)[16][64], float (&Bs)[16][64]) {
    const int tid = threadIdx.x;
    const int tx = tid & 15, ty = tid >> 4;
    const int rowBase = (blockIdx.x >> 5) * 64;   // 4 row tiles
    const int colBase = (blockIdx.x & 31) * 64;   // 32 col tiles

    float acc[4][4];
    #pragma unroll
    for (int i = 0; i < 4; i++)
        #pragma unroll
        for (int j = 0; j < 4; j++) acc[i][j] = 0.f;

    for (int k0 = 0; k0 < KK; k0 += 16) {
        {
            int r  = tid >> 2;
            int kq = (tid & 3) << 2;
            float4 v = *(const float4*)&g_A[(size_t)(rowBase + r) * KK + k0 + kq];
            As[kq + 0][r] = v.x; As[kq + 1][r] = v.y;
            As[kq + 2][r] = v.z; As[kq + 3][r] = v.w;
        }
        {
            int kr = tid >> 4;
            int nq = (tid & 15) << 2;
            *(float4*)&Bs[kr][nq] = *(const float4*)&W[(size_t)(k0 + kr) * ZZ + colBase + nq];
        }
        __syncthreads();
        #pragma unroll
        for (int k = 0; k < 16; k++) {
            float4 a4 = *(const float4*)&As[k][ty << 2];
            float4 b4 = *(const float4*)&Bs[k][tx << 2];
            float a[4] = {a4.x, a4.y, a4.z, a4.w};
            float bb[4] = {b4.x, b4.y, b4.z, b4.w};
            #pragma unroll
            for (int i = 0; i < 4; i++)
                #pragma unroll
                for (int j = 0; j < 4; j++)
                    acc[i][j] = fmaf(a[i], bb[j], acc[i][j]);
        }
        __syncthreads();
    }

    #pragma unroll
    for (int i = 0; i < 4; i++) {
        int row = rowBase + (ty << 2) + i;
        int col = colBase + (tx << 2);
        float4 bv = *(const float4*)&bias[col];
        float4 o;
        o.x = acc[i][0] + bv.x; o.y = acc[i][1] + bv.y;
        o.z = acc[i][2] + bv.z; o.w = acc[i][3] + bv.w;
        *(float4*)&g_Z[(size_t)row * ZZ + col] = o;
    }
}

// ---------------- persistent encoder: 256 LSTM steps ----------------
__global__ void __launch_bounds__(THR, 1) encoder_kernel(const float* __restrict__ bias) {
    __shared__ float As[16][64];
    __shared__ float Bs[16][64];
    unsigned gen = 0;

    for (int t = 0; t < TT; t++) {
        gemm_tile(g_Wenc, bias, As, Bs);
        gsync(++gen);

        int base = blockIdx.x * (BB * UU / GRID) + threadIdx.x;
        #pragma unroll
        for (int i = 0; i < (BB * UU / GRID) / THR; i++) {
            int idx = base + i * THR;
            int b = idx >> 9, u = idx & 511;
            const float* zr = &g_Z[(size_t)b * ZZ];
            float zi = zr[u], zf = zr[u + UU], zg = zr[u + 2 * UU], zo = zr[u + 3 * UU];
            float c = sigf(zf) * g_c[idx] + sigf(zi) * tanhf(zg);
            float h = sigf(zo) * tanhf(c);
            g_c[idx] = c;
            g_h[idx] = h;
            g_enc[((size_t)b * TT + t) * UU + u] = h;        // [b][t][u]
            g_A[b * KK + UU + u] = h;
            if (t + 1 < TT)
                g_A[b * KK + u] = g_Xt[(size_t)(t + 1) * (BB * UU) + idx];
        }
        gsync(++gen);
    }
}

// ---------------- persistent decoder: 256 steps (GEMM + gates + attention) ----------------
__global__ void __launch_bounds__(THR, 1) decoder_kernel(
    const float* __restrict__ bias,
    const float* __restrict__ ptr_w, const float* __restrict__ ptr_b,
    float* __restrict__ out)
{
    __shared__ float As[16][64];
    __shared__ float Bs[16][64];
    __shared__ float hs[UU];
    __shared__ float sc[TT];
    __shared__ float red[16];

    unsigned gen = 2 * TT;   // encoder performed exactly 2*TT syncs

    // A x-half = dec_in0 (h-half already holds encoder final h)
    {
        int base = blockIdx.x * (BB * UU / GRID) + threadIdx.x;
        #pragma unroll
        for (int i = 0; i < (BB * UU / GRID) / THR; i++) {
            int idx = base + i * THR;
            int b = idx >> 9, u = idx & 511;
            g_A[b * KK + u] = g_x0[idx];
        }
    }
    gsync(++gen);

    const float w  = *ptr_w;
    const float pb = *ptr_b;
    const int tid = threadIdx.x;
    const int warp = tid >> 5, lane = tid & 31;

    for (int s = 0; s < TT; s++) {
        gemm_tile(g_Wdec, bias, As, Bs);
        gsync(++gen);

        // gates
        {
            int base = blockIdx.x * (BB * UU / GRID) + threadIdx.x;
            #pragma unroll
            for (int i = 0; i < (BB * UU / GRID) / THR; i++) {
                int idx = base + i * THR;
                int b = idx >> 9, u = idx & 511;
                const float* zr = &g_Z[(size_t)b * ZZ];
                float zi = zr[u], zf = zr[u + UU], zg = zr[u + 2 * UU], zo = zr[u + 3 * UU];
                float c = sigf(zf) * g_c[idx] + sigf(zi) * tanhf(zg);
                float h = sigf(zo) * tanhf(c);
                g_c[idx] = c;
                g_h[idx] = h;
                g_A[b * KK + UU + u] = h;
            }
        }
        gsync(++gen);

        // attention: each CTA handles 2 batch rows
        for (int rb = 0; rb < 2; rb++) {
            int b = blockIdx.x * 2 + rb;

            hs[tid] = g_h[b * UU + tid];
            hs[tid + 256] = g_h[b * UU + 256 + tid];
            __syncthreads();

            // scores: warp per t
            const float4* hs4 = (const float4*)hs;
            for (int t = warp; t < TT; t += 8) {
                const float4* ep4 = (const float4*)&g_enc[((size_t)b * TT + t) * UU];
                float acc = 0.f;
                #pragma unroll
                for (int k = 0; k < 4; k++) {
                    float4 e = ep4[lane + 32 * k];
                    float4 hh = hs4[lane + 32 * k];
                    acc = fmaf(e.x, hh.x, fmaf(e.y, hh.y, fmaf(e.z, hh.z, fmaf(e.w, hh.w, acc))));
                }
                #pragma unroll
                for (int o = 16; o; o >>= 1) acc += __shfl_xor_sync(0xFFFFFFFFu, acc, o);
                if (!lane) sc[t] = acc * w + pb;
            }
            __syncthreads();

            // softmax over 256 scores, one per thread
            float v = sc[tid];
            float m = v;
            #pragma unroll
            for (int o = 16; o; o >>= 1) m = fmaxf(m, __shfl_xor_sync(0xFFFFFFFFu, m, o));
            if (!lane) red[warp] = m;
            __syncthreads();
            if (tid == 0) {
                float mm = red[0];
                #pragma unroll
                for (int i = 1; i < 8; i++) mm = fmaxf(mm, red[i]);
                red[8] = mm;
            }
            __syncthreads();
            float e = expf(v - red[8]);
            float sum = e;
            #pragma unroll
            for (int o = 16; o; o >>= 1) sum += __shfl_xor_sync(0xFFFFFFFFu, sum, o);
            if (!lane) red[warp] = sum;
            __syncthreads();
            if (tid == 0) {
                float ss = 0.f;
                #pragma unroll
                for (int i = 0; i < 8; i++) ss += red[i];
                red[9] = ss;
            }
            __syncthreads();
            float p = e / red[9];
            sc[tid] = p;
            out[(size_t)b * (TT * TT) + (size_t)s * TT + tid] = p;
            __syncthreads();

            // context
            float a0 = 0.f, a1 = 0.f;
            #pragma unroll 4
            for (int t = 0; t < TT; t++) {
                const float* ep = &g_enc[((size_t)b * TT + t) * UU];
                float pt = sc[t];
                a0 = fmaf(pt, ep[tid], a0);
                a1 = fmaf(pt, ep[tid + 256], a1);
            }
            g_A[b * KK + tid] = a0;
            g_A[b * KK + 256 + tid] = a1;
            __syncthreads();
        }
        gsync(++gen);
    }
}

// ---------------- launch: 7 graph nodes total ----------------
extern "C" void kernel_launch(void* const* d_in, const int* in_sizes, int n_in,
                              void* d_out, int out_size) {
    const float* inputs = (const float*)d_in[0];
    const float* score  = (const float*)d_in[1];
    const float* enc_Wx = (const float*)d_in[2];
    const float* enc_Wh = (const float*)d_in[3];
    const float* enc_b  = (const float*)d_in[4];
    const float* dec_Wx = (const float*)d_in[5];
    const float* dec_Wh = (const float*)d_in[6];
    const float* dec_b  = (const float*)d_in[7];
    const float* ptr_w  = (const float*)d_in[8];
    const float* ptr_b  = (const float*)d_in[9];
    float* out = (float*)d_out;

    float* Wenc; cudaGetSymbolAddress((void**)&Wenc, g_Wenc);
    float* Wdec; cudaGetSymbolAddress((void**)&Wdec, g_Wdec);

    prep_w_kernel<<<(KK * ZZ + THR - 1) / THR, THR>>>(Wenc, enc_Wx, enc_Wh);
    prep_w_kernel<<<(KK * ZZ + THR - 1) / THR, THR>>>(Wdec, dec_Wx, dec_Wh);
    prep_x_kernel<<<(int)(((size_t)TT * BB * UU + THR - 1) / THR), THR>>>(inputs, score);
    mean_kernel<<<(BB * UU + THR - 1) / THR, THR>>>();
    init_kernel<<<(BB * KK + THR - 1) / THR, THR>>>();

    encoder_kernel<<<GRID, THR>>>(enc_b);
    decoder_kernel<<<GRID, THR>>>(dec_b, ptr_w, ptr_b, out);
}

// round 3
// speedup vs baseline: 2.3219x; 2.3219x over previous
#include <cuda_runtime.h>
#include <math.h>

#define BB 256       // batch
#define TT 256       // timesteps
#define FF 511       // raw feature dim
#define UU 512       // units
#define ZZ 2048      // 4*U (interleaved gate columns: n' = 4u + gate)
#define KK 1024      // fused K = U (x) + U (h)
#define GRID 128     // persistent grid
#define THR 256

// ---------------- device scratch ----------------
__device__ float g_Xt[(size_t)TT * BB * UU];    // [t][b][u] tf32-rounded input (score appended)
__device__ float g_enc[(size_t)BB * TT * UU];   // [b][t][u] encoder hidden (fp32)
__device__ float g_Wenc[(size_t)KK * ZZ];       // [Wx;Wh], gate-interleaved cols, tf32-rounded
__device__ float g_Wdec[(size_t)KK * ZZ];
__device__ float g_Benc[ZZ];                    // gate-interleaved bias
__device__ float g_Bdec[ZZ];
__device__ float g_A[2][BB * KK];               // double-buffered GEMM operand [x | h], tf32
__device__ float g_h[BB * UU];                  // fp32 h (decoder attention)
__device__ float g_c[BB * UU];
__device__ float g_x0[BB * UU];                 // decoder initial input
__device__ unsigned g_cnt, g_gen;

// ---------------- helpers ----------------
__device__ __forceinline__ float tf32r(float x) {
    unsigned r; asm("cvt.rna.tf32.f32 %0, %1;" : "=r"(r) : "f"(x));
    return __uint_as_float(r);
}
__device__ __forceinline__ float sigf(float x) { return 1.0f / (1.0f + __expf(-x)); }
__device__ __forceinline__ float tanhx(float x) { return 2.0f / (1.0f + __expf(-2.0f * x)) - 1.0f; }

__device__ __forceinline__ void gsync(unsigned target) {
    __syncthreads();
    if (threadIdx.x == 0) {
        __threadfence();
        unsigned t = atomicAdd(&g_cnt, 1u);
        if (t == GRID - 1u) {
            g_cnt = 0u;
            __threadfence();
            atomicExch(&g_gen, target);
        } else {
            while (atomicAdd(&g_gen, 0u) < target) __nanosleep(32);
            __threadfence();
        }
    }
    __syncthreads();
}

// ---------------- prep kernels ----------------
__global__ void prep_x_kernel(const float* __restrict__ inputs, const float* __restrict__ score) {
    size_t idx = (size_t)blockIdx.x * blockDim.x + threadIdx.x;
    if (idx >= (size_t)TT * BB * UU) return;
    int t = (int)(idx / (BB * UU));
    int rem = (int)(idx % (BB * UU));
    int b = rem / UU, u = rem % UU;
    float v = (u < FF) ? inputs[((size_t)b * TT + t) * FF + u] : score[b];
    g_Xt[idx] = tf32r(v);
}

__global__ void mean_kernel() {
    int idx = blockIdx.x * blockDim.x + threadIdx.x;
    if (idx >= BB * UU) return;
    float s = 0.f;
    #pragma unroll 4
    for (int t = 0; t < TT; t++) s += g_Xt[(size_t)t * (BB * UU) + idx];
    g_x0[idx] = tf32r(s * (1.0f / TT));
}

// gate-interleave columns + tf32-round:  dst[k][4u+g] = src[k][g*512+u]
__global__ void prep_w_kernel(float* __restrict__ dst,
                              const float* __restrict__ Wx, const float* __restrict__ Wh) {
    size_t idx = (size_t)blockIdx.x * blockDim.x + threadIdx.x;
    if (idx >= (size_t)KK * ZZ) return;
    int k = (int)(idx / ZZ);
    int np = (int)(idx % ZZ);
    int u = np >> 2, gate = np & 3;
    int n = gate * UU + u;
    float v = (k < UU) ? Wx[(size_t)k * ZZ + n] : Wh[(size_t)(k - UU) * ZZ + n];
    dst[idx] = tf32r(v);
}

__global__ void prep_bias_kernel(const float* __restrict__ be, const float* __restrict__ bd) {
    int np = blockIdx.x * blockDim.x + threadIdx.x;
    if (np >= ZZ) return;
    int u = np >> 2, gate = np & 3;
    g_Benc[np] = be[gate * UU + u];
    g_Bdec[np] = bd[gate * UU + u];
}

__global__ void init_kernel() {
    int idx = blockIdx.x * blockDim.x + threadIdx.x;   // over B*K
    if (idx == 0) { g_cnt = 0u; g_gen = 0u; }
    if (idx >= BB * KK) return;
    int b = idx / KK, col = idx % KK;
    if (col < UU) {
        g_A[0][idx] = g_Xt[(size_t)b * UU + col];   // Xt[t=0]
    } else {
        g_A[0][idx] = 0.f;
        g_c[b * UU + (col - UU)] = 0.f;
    }
}

// ---------------- tf32 tensor-core GEMM + fused gates ----------------
// CTA tile 64x64, 8 warps as 2(M)x4(N), warp tile 32x16, mma m16n8k8.
struct SmemGemm {
    float SA[2][64 * 20];   // [row][k] stride 20: conflict-free frag loads
    float SB[2][16 * 72];   // [k][n]  stride 72: conflict-free frag loads
};

__device__ __forceinline__ void mma_tf32(float d[4], const unsigned a[4], const unsigned b[2]) {
    asm volatile("mma.sync.aligned.m16n8k8.row.col.f32.tf32.tf32.f32 "
                 "{%0,%1,%2,%3}, {%4,%5,%6,%7}, {%8,%9}, {%0,%1,%2,%3};\n"
                 : "+f"(d[0]), "+f"(d[1]), "+f"(d[2]), "+f"(d[3])
                 : "r"(a[0]), "r"(a[1]), "r"(a[2]), "r"(a[3]), "r"(b[0]), "r"(b[1]));
}

__device__ __forceinline__ void compute_stage(const float* __restrict__ sA,
                                              const float* __restrict__ sB,
                                              int mB, int nB, int gq, int tq,
                                              float d[2][2][4]) {
    #pragma unroll
    for (int kc = 0; kc < 16; kc += 8) {
        unsigned a0[4], a1[4], b0[2], b1[2];
        const float* A0 = sA + (mB + gq) * 20 + kc + tq;
        a0[0] = __float_as_uint(A0[0]);
        a0[1] = __float_as_uint(A0[8 * 20]);
        a0[2] = __float_as_uint(A0[4]);
        a0[3] = __float_as_uint(A0[8 * 20 + 4]);
        const float* A1 = A0 + 16 * 20;
        a1[0] = __float_as_uint(A1[0]);
        a1[1] = __float_as_uint(A1[8 * 20]);
        a1[2] = __float_as_uint(A1[4]);
        a1[3] = __float_as_uint(A1[8 * 20 + 4]);
        const float* B0 = sB + (kc + tq) * 72 + nB + gq;
        b0[0] = __float_as_uint(B0[0]);
        b0[1] = __float_as_uint(B0[4 * 72]);
        b1[0] = __float_as_uint(B0[8]);
        b1[1] = __float_as_uint(B0[4 * 72 + 8]);
        mma_tf32(d[0][0], a0, b0);
        mma_tf32(d[0][1], a0, b1);
        mma_tf32(d[1][0], a1, b0);
        mma_tf32(d[1][1], a1, b1);
    }
}

template<bool ENC>
__device__ __forceinline__ void do_cell(int b, int u, float zi, float zf, float zg, float zo,
                                        float* __restrict__ Anext, int t) {
    int idx = b * UU + u;
    float co = g_c[idx];
    float i = sigf(zi), f = sigf(zf), gg = tanhx(zg), o = sigf(zo);
    float c = f * co + i * gg;
    float h = o * tanhx(c);
    g_c[idx] = c;
    Anext[b * KK + UU + u] = tf32r(h);
    if (ENC) g_enc[((size_t)b * TT + t) * UU + u] = h;
    else     g_h[idx] = h;
}

template<bool ENC>
__device__ __forceinline__ void lstm_step(const float* __restrict__ Acur,
                                          float* __restrict__ Anext,
                                          const float* __restrict__ W,
                                          const float* __restrict__ bias,
                                          SmemGemm& sm, int t) {
    const int tid = threadIdx.x;
    const int lane = tid & 31, wid = tid >> 5;
    const int rowBase = (blockIdx.x >> 5) << 6;
    const int colBase = (blockIdx.x & 31) << 6;
    const int mB = (wid >> 2) << 5;        // 0 / 32
    const int nB = (wid & 3) << 4;         // 0,16,32,48
    const int gq = lane >> 2, tq = lane & 3;

    const int arow = tid >> 2;             // 0..63
    const int akq  = (tid & 3) << 2;       // 0,4,8,12
    const int bkr  = tid >> 4;             // 0..15
    const int bnq  = (tid & 15) << 2;      // 0..60

    const float* aptr = Acur + (size_t)(rowBase + arow) * KK + akq;
    const float* bptr = W + (size_t)bkr * ZZ + colBase + bnq;

    // pipeline prologue: tiles 0,1 into regs; tile 0 -> smem stage 0
    float4 ra0 = *(const float4*)(aptr);
    float4 rb0 = *(const float4*)(bptr);
    float4 ra1 = *(const float4*)(aptr + 16);
    float4 rb1 = *(const float4*)(bptr + (size_t)16 * ZZ);
    *(float4*)&sm.SA[0][arow * 20 + akq] = ra0;
    *(float4*)&sm.SB[0][bkr * 72 + bnq] = rb0;
    __syncthreads();

    float d[2][2][4];
    #pragma unroll
    for (int i = 0; i < 2; i++)
        #pragma unroll
        for (int j = 0; j < 2; j++)
            #pragma unroll
            for (int q = 0; q < 4; q++) d[i][j][q] = 0.f;

    #pragma unroll 1
    for (int kt = 0; kt < 64; kt += 2) {
        if (kt + 2 < 64) {
            ra0 = *(const float4*)(aptr + (kt + 2) * 16);
            rb0 = *(const float4*)(bptr + (size_t)(kt + 2) * 16 * ZZ);
        }
        compute_stage(sm.SA[0], sm.SB[0], mB, nB, gq, tq, d);
        *(float4*)&sm.SA[1][arow * 20 + akq] = ra1;
        *(float4*)&sm.SB[1][bkr * 72 + bnq] = rb1;
        __syncthreads();

        if (kt + 3 < 64) {
            ra1 = *(const float4*)(aptr + (kt + 3) * 16);
            rb1 = *(const float4*)(bptr + (size_t)(kt + 3) * 16 * ZZ);
        }
        compute_stage(sm.SA[1], sm.SB[1], mB, nB, gq, tq, d);
        if (kt + 2 < 64) {
            *(float4*)&sm.SA[0][arow * 20 + akq] = ra0;
            *(float4*)&sm.SB[0][bkr * 72 + bnq] = rb0;
        }
        __syncthreads();
    }

    // fused gate epilogue: cols are (i,f,g,o) interleaved; lane pair (t, t^1)
    // holds (i,f)/(g,o) of the same u -> one shfl_xor(1) exchange.
    #pragma unroll
    for (int ms = 0; ms < 2; ms++) {
        #pragma unroll
        for (int ns = 0; ns < 2; ns++) {
            int c0 = colBase + nB + ns * 8 + 2 * tq;
            float bv0 = bias[c0], bv1 = bias[c0 + 1];
            float z0 = d[ms][ns][0] + bv0;
            float z1 = d[ms][ns][1] + bv1;
            float z2 = d[ms][ns][2] + bv0;
            float z3 = d[ms][ns][3] + bv1;
            float p0 = __shfl_xor_sync(0xffffffffu, z0, 1);
            float p1 = __shfl_xor_sync(0xffffffffu, z1, 1);
            float p2 = __shfl_xor_sync(0xffffffffu, z2, 1);
            float p3 = __shfl_xor_sync(0xffffffffu, z3, 1);
            if (!(tq & 1)) {
                int u = c0 >> 2;
                int r0 = rowBase + mB + ms * 16 + gq;
                do_cell<ENC>(r0,     u, z0, z1, p0, p1, Anext, t);
                do_cell<ENC>(r0 + 8, u, z2, z3, p2, p3, Anext, t);
            }
        }
    }
}

// ---------------- persistent encoder ----------------
__global__ void __launch_bounds__(THR, 1) encoder_kernel() {
    __shared__ SmemGemm sm;
    unsigned gen = 0;
    for (int t = 0; t < TT; t++) {
        const float* Acur = g_A[t & 1];
        float* Anext = g_A[(t + 1) & 1];
        if (t + 1 < TT) {
            int base = blockIdx.x * (BB * UU / GRID) + threadIdx.x;
            #pragma unroll
            for (int i = 0; i < (BB * UU / GRID) / THR; i++) {
                int idx = base + i * THR;
                int b = idx >> 9, u = idx & 511;
                Anext[b * KK + u] = g_Xt[(size_t)(t + 1) * (BB * UU) + idx];
            }
        }
        lstm_step<true>(Acur, Anext, g_Wenc, g_Benc, sm, t);
        gsync(++gen);
    }
}

// ---------------- persistent decoder (GEMM+gates, then single-pass attention) ----
struct SmemDec {
    SmemGemm g;
    float wctx[8][UU];
    float sc[TT];
    float wm[8];
    float wz[8];
};

__global__ void __launch_bounds__(THR, 1) decoder_kernel(
    const float* __restrict__ ptr_w, const float* __restrict__ ptr_b,
    float* __restrict__ out) {
    __shared__ SmemDec sm;
    unsigned gen = TT;

    // prologue: A[0] x-half = dec_in0
    {
        int base = blockIdx.x * (BB * UU / GRID) + threadIdx.x;
        #pragma unroll
        for (int i = 0; i < (BB * UU / GRID) / THR; i++) {
            int idx = base + i * THR;
            int b = idx >> 9, u = idx & 511;
            g_A[0][b * KK + u] = g_x0[idx];
        }
    }
    gsync(++gen);

    const float w  = *ptr_w;
    const float pb = *ptr_b;
    const int tid = threadIdx.x, lane = tid & 31, warp = tid >> 5;

    for (int s = 0; s < TT; s++) {
        const float* Acur = g_A[s & 1];
        float* Anext = g_A[(s + 1) & 1];
        lstm_step<false>(Acur, Anext, g_Wdec, g_Bdec, sm.g, s);
        gsync(++gen);

        // online-softmax attention: single pass over enc; 2 rows per CTA
        for (int rb = 0; rb < 2; rb++) {
            int b = blockIdx.x * 2 + rb;
            const float4* hb = (const float4*)&g_h[b * UU];
            float4 h0 = hb[lane], h1 = hb[lane + 32], h2 = hb[lane + 64], h3 = hb[lane + 96];

            float m = -3.0e38f, Zw = 0.f;
            float4 c0 = {0.f,0.f,0.f,0.f}, c1 = c0, c2 = c0, c3 = c0;

            for (int t = warp; t < TT; t += 8) {
                const float4* ep = (const float4*)&g_enc[((size_t)b * TT + t) * UU];
                float4 e0 = ep[lane], e1 = ep[lane + 32], e2 = ep[lane + 64], e3 = ep[lane + 96];
                float sd = e0.x*h0.x + e0.y*h0.y + e0.z*h0.z + e0.w*h0.w
                         + e1.x*h1.x + e1.y*h1.y + e1.z*h1.z + e1.w*h1.w
                         + e2.x*h2.x + e2.y*h2.y + e2.z*h2.z + e2.w*h2.w
                         + e3.x*h3.x + e3.y*h3.y + e3.z*h3.z + e3.w*h3.w;
                #pragma unroll
                for (int o = 16; o; o >>= 1) sd += __shfl_xor_sync(0xffffffffu, sd, o);
                float sv = sd * w + pb;
                if (lane == 0) sm.sc[t] = sv;
                float mn = fmaxf(m, sv);
                float scale = __expf(m - mn);
                float es = __expf(sv - mn);
                Zw = Zw * scale + es;
                c0.x = c0.x*scale + es*e0.x; c0.y = c0.y*scale + es*e0.y;
                c0.z = c0.z*scale + es*e0.z; c0.w = c0.w*scale + es*e0.w;
                c1.x = c1.x*scale + es*e1.x; c1.y = c1.y*scale + es*e1.y;
                c1.z = c1.z*scale + es*e1.z; c1.w = c1.w*scale + es*e1.w;
                c2.x = c2.x*scale + es*e2.x; c2.y = c2.y*scale + es*e2.y;
                c2.z = c2.z*scale + es*e2.z; c2.w = c2.w*scale + es*e2.w;
                c3.x = c3.x*scale + es*e3.x; c3.y = c3.y*scale + es*e3.y;
                c3.z = c3.z*scale + es*e3.z; c3.w = c3.w*scale + es*e3.w;
                m = mn;
            }
            if (lane == 0) { sm.wm[warp] = m; sm.wz[warp] = Zw; }
            float4* wc = (float4*)sm.wctx[warp];
            wc[lane] = c0; wc[lane + 32] = c1; wc[lane + 64] = c2; wc[lane + 96] = c3;
            __syncthreads();

            // combine 8 warps
            float M = sm.wm[0];
            #pragma unroll
            for (int q = 1; q < 8; q++) M = fmaxf(M, sm.wm[q]);
            float Zt = 0.f, x0a = 0.f, x1a = 0.f;
            #pragma unroll
            for (int q = 0; q < 8; q++) {
                float e = __expf(sm.wm[q] - M);
                Zt += e * sm.wz[q];
                x0a += e * sm.wctx[q][tid];
                x1a += e * sm.wctx[q][tid + 256];
            }
            float invZ = 1.0f / Zt;
            Anext[b * KK + tid]       = tf32r(x0a * invZ);
            Anext[b * KK + 256 + tid] = tf32r(x1a * invZ);
            out[(size_t)b * (TT * TT) + (size_t)s * TT + tid] = __expf(sm.sc[tid] - M) * invZ;
            __syncthreads();
        }
        gsync(++gen);
    }
}

// ---------------- launch: 8 graph nodes ----------------
extern "C" void kernel_launch(void* const* d_in, const int* in_sizes, int n_in,
                              void* d_out, int out_size) {
    const float* inputs = (const float*)d_in[0];
    const float* score  = (const float*)d_in[1];
    const float* enc_Wx = (const float*)d_in[2];
    const float* enc_Wh = (const float*)d_in[3];
    const float* enc_b  = (const float*)d_in[4];
    const float* dec_Wx = (const float*)d_in[5];
    const float* dec_Wh = (const float*)d_in[6];
    const float* dec_b  = (const float*)d_in[7];
    const float* ptr_w  = (const float*)d_in[8];
    const float* ptr_b  = (const float*)d_in[9];
    float* out = (float*)d_out;

    float* Wenc; cudaGetSymbolAddress((void**)&Wenc, g_Wenc);
    float* Wdec; cudaGetSymbolAddress((void**)&Wdec, g_Wdec);

    prep_w_kernel<<<(KK * ZZ + THR - 1) / THR, THR>>>(Wenc, enc_Wx, enc_Wh);
    prep_w_kernel<<<(KK * ZZ + THR - 1) / THR, THR>>>(Wdec, dec_Wx, dec_Wh);
    prep_bias_kernel<<<(ZZ + THR - 1) / THR, THR>>>(enc_b, dec_b);
    prep_x_kernel<<<(int)(((size_t)TT * BB * UU + THR - 1) / THR), THR>>>(inputs, score);
    mean_kernel<<<(BB * UU + THR - 1) / THR, THR>>>();
    init_kernel<<<(BB * KK + THR - 1) / THR, THR>>>();

    encoder_kernel<<<GRID, THR>>>();
    decoder_kernel<<<GRID, THR>>>(ptr_w, ptr_b, out);
}

// round 4
// speedup vs baseline: 3.3656x; 1.4495x over previous
#include <cuda_runtime.h>
#include <cuda_fp16.h>
#include <math.h>

#define BB 256       // batch
#define TT 256       // timesteps
#define FF 511       // raw feature dim
#define UU 512       // units
#define ZZ 2048      // 4*U (gate-interleaved cols: n' = 4u + gate)
#define KK 1024      // decoder fused K
#define GRID 128     // persistent grid
#define THR 256

// ---------------- device scratch ----------------
__device__ float g_Xt[(size_t)TT * BB * UU];     // [t][b][u] tf32 input (score appended)
__device__ float g_Zx[(size_t)TT * BB * ZZ];     // precomputed x@Wx + bias (gate-interleaved)
__device__ __half g_encH[(size_t)BB * TT * UU];  // [b][t][u] encoder hidden, fp16
__device__ float g_Wxe[(size_t)UU * ZZ];         // enc Wx, interleaved, tf32
__device__ float g_Whe[(size_t)UU * ZZ];         // enc Wh, interleaved, tf32
__device__ float g_Wdec[(size_t)KK * ZZ];        // [Wx;Wh] stacked, interleaved, tf32
__device__ float g_Bdec[ZZ];
__device__ float g_Ah[2][BB * UU];               // encoder h operand (tf32), double-buffered
__device__ float g_Ad[2][BB * KK];               // decoder [xin|h] operand (tf32)
__device__ float g_h[BB * UU];                   // fp32 h for attention
__device__ float g_c[BB * UU];
__device__ float g_x0[BB * UU];
__device__ unsigned g_cnt, g_gen;

// ---------------- helpers ----------------
__device__ __forceinline__ float tf32r(float x) {
    unsigned r; asm("cvt.rna.tf32.f32 %0, %1;" : "=r"(r) : "f"(x));
    return __uint_as_float(r);
}
__device__ __forceinline__ float sigf(float x) { return 1.0f / (1.0f + __expf(-x)); }
__device__ __forceinline__ float tanhx(float x) { return 2.0f / (1.0f + __expf(-2.0f * x)) - 1.0f; }
__device__ __forceinline__ void h2f(unsigned v, float& a, float& b) {
    float2 f = __half22float2(*reinterpret_cast<const __half2*>(&v));
    a = f.x; b = f.y;
}

__device__ __forceinline__ void gsync(unsigned target) {
    __syncthreads();
    if (threadIdx.x == 0) {
        __threadfence();
        unsigned t = atomicAdd(&g_cnt, 1u);
        if (t == GRID - 1u) {
            g_cnt = 0u;
            __threadfence();
            atomicExch(&g_gen, target);
        } else {
            while (atomicAdd(&g_gen, 0u) < target) __nanosleep(32);
            __threadfence();
        }
    }
    __syncthreads();
}

__device__ __forceinline__ void mma_tf32(float d[4], const unsigned a[4], const unsigned b[2]) {
    asm volatile("mma.sync.aligned.m16n8k8.row.col.f32.tf32.tf32.f32 "
                 "{%0,%1,%2,%3}, {%4,%5,%6,%7}, {%8,%9}, {%0,%1,%2,%3};\n"
                 : "+f"(d[0]), "+f"(d[1]), "+f"(d[2]), "+f"(d[3])
                 : "r"(a[0]), "r"(a[1]), "r"(a[2]), "r"(a[3]), "r"(b[0]), "r"(b[1]));
}

// ---------------- prep kernels ----------------
__global__ void prep_x_kernel(const float* __restrict__ inputs, const float* __restrict__ score) {
    size_t idx = (size_t)blockIdx.x * blockDim.x + threadIdx.x;
    if (idx >= (size_t)TT * BB * UU) return;
    int t = (int)(idx / (BB * UU));
    int rem = (int)(idx % (BB * UU));
    int b = rem / UU, u = rem % UU;
    float v = (u < FF) ? inputs[((size_t)b * TT + t) * FF + u] : score[b];
    g_Xt[idx] = tf32r(v);
}

__global__ void mean_kernel() {
    int idx = blockIdx.x * blockDim.x + threadIdx.x;
    if (idx >= BB * UU) return;
    float s = 0.f;
    #pragma unroll 4
    for (int t = 0; t < TT; t++) s += g_Xt[(size_t)t * (BB * UU) + idx];
    g_x0[idx] = tf32r(s * (1.0f / TT));
}

__global__ void prep_w_enc(const float* __restrict__ Wx, const float* __restrict__ Wh) {
    size_t idx = (size_t)blockIdx.x * blockDim.x + threadIdx.x;
    if (idx >= (size_t)UU * ZZ) return;
    int k = (int)(idx / ZZ), np = (int)(idx % ZZ);
    int u = np >> 2, gate = np & 3;
    int n = gate * UU + u;
    g_Wxe[idx] = tf32r(Wx[(size_t)k * ZZ + n]);
    g_Whe[idx] = tf32r(Wh[(size_t)k * ZZ + n]);
}

__global__ void prep_w_dec(const float* __restrict__ Wx, const float* __restrict__ Wh) {
    size_t idx = (size_t)blockIdx.x * blockDim.x + threadIdx.x;
    if (idx >= (size_t)KK * ZZ) return;
    int k = (int)(idx / ZZ), np = (int)(idx % ZZ);
    int u = np >> 2, gate = np & 3;
    int n = gate * UU + u;
    float v = (k < UU) ? Wx[(size_t)k * ZZ + n] : Wh[(size_t)(k - UU) * ZZ + n];
    g_Wdec[idx] = tf32r(v);
}

__global__ void prep_bias_kernel(const float* __restrict__ bd) {
    int np = blockIdx.x * blockDim.x + threadIdx.x;
    if (np >= ZZ) return;
    g_Bdec[np] = bd[(np & 3) * UU + (np >> 2)];
}

__global__ void init_kernel() {
    int idx = blockIdx.x * blockDim.x + threadIdx.x;   // over B*U
    if (idx == 0) { g_cnt = 0u; g_gen = 0u; }
    if (idx >= BB * UU) return;
    g_Ah[0][idx] = 0.f;
    g_c[idx] = 0.f;
}

// ---------------- Zx = X @ Wxe + bias : one big parallel GEMM ----------------
// CTA tile 128(M)x64(N), K=512. 8 warps = 4(M)x2(N), warp tile 32x32.
__global__ void __launch_bounds__(256) zx_kernel(const float* __restrict__ be) {
    __shared__ float SA[2][128 * 20];
    __shared__ float SB[2][16 * 72];
    const int tid = threadIdx.x, lane = tid & 31, wid = tid >> 5;
    const int rowBase = blockIdx.y << 7;
    const int colBase = blockIdx.x << 6;
    const int mB = (wid >> 1) << 5;
    const int nB = (wid & 1) << 5;
    const int gq = lane >> 2, tq = lane & 3;

    const int ar = tid >> 2;             // 0..63 (and +64)
    const int akq = (tid & 3) << 2;
    const int bkr = tid >> 4, bnq = (tid & 15) << 2;
    const float* aptrA = g_Xt + (size_t)(rowBase + ar) * UU + akq;
    const float* aptrB = aptrA + (size_t)64 * UU;
    const float* bptr = g_Wxe + (size_t)bkr * ZZ + colBase + bnq;

    float4 rAa0 = *(const float4*)(aptrA);
    float4 rAb0 = *(const float4*)(aptrB);
    float4 rB0  = *(const float4*)(bptr);
    float4 rAa1 = *(const float4*)(aptrA + 16);
    float4 rAb1 = *(const float4*)(aptrB + 16);
    float4 rB1  = *(const float4*)(bptr + (size_t)16 * ZZ);
    *(float4*)&SA[0][ar * 20 + akq] = rAa0;
    *(float4*)&SA[0][(64 + ar) * 20 + akq] = rAb0;
    *(float4*)&SB[0][bkr * 72 + bnq] = rB0;
    __syncthreads();

    float d[2][4][4];
    #pragma unroll
    for (int i = 0; i < 2; i++)
        #pragma unroll
        for (int j = 0; j < 4; j++)
            #pragma unroll
            for (int q = 0; q < 4; q++) d[i][j][q] = 0.f;

    #pragma unroll 1
    for (int kt = 0; kt < 32; kt += 2) {
        if (kt + 2 < 32) {
            rAa0 = *(const float4*)(aptrA + (kt + 2) * 16);
            rAb0 = *(const float4*)(aptrB + (kt + 2) * 16);
            rB0  = *(const float4*)(bptr + (size_t)(kt + 2) * 16 * ZZ);
        }
        // compute stage 0
        #pragma unroll
        for (int kc = 0; kc < 16; kc += 8) {
            unsigned a0[4], a1[4], bb[4][2];
            const float* A0 = SA[0] + (mB + gq) * 20 + kc + tq;
            a0[0] = __float_as_uint(A0[0]);      a0[1] = __float_as_uint(A0[8 * 20]);
            a0[2] = __float_as_uint(A0[4]);      a0[3] = __float_as_uint(A0[8 * 20 + 4]);
            const float* A1 = A0 + 16 * 20;
            a1[0] = __float_as_uint(A1[0]);      a1[1] = __float_as_uint(A1[8 * 20]);
            a1[2] = __float_as_uint(A1[4]);      a1[3] = __float_as_uint(A1[8 * 20 + 4]);
            const float* B0 = SB[0] + (kc + tq) * 72 + nB + gq;
            #pragma unroll
            for (int ns = 0; ns < 4; ns++) {
                bb[ns][0] = __float_as_uint(B0[ns * 8]);
                bb[ns][1] = __float_as_uint(B0[4 * 72 + ns * 8]);
            }
            #pragma unroll
            for (int ns = 0; ns < 4; ns++) { mma_tf32(d[0][ns], a0, bb[ns]); mma_tf32(d[1][ns], a1, bb[ns]); }
        }
        *(float4*)&SA[1][ar * 20 + akq] = rAa1;
        *(float4*)&SA[1][(64 + ar) * 20 + akq] = rAb1;
        *(float4*)&SB[1][bkr * 72 + bnq] = rB1;
        __syncthreads();

        if (kt + 3 < 32) {
            rAa1 = *(const float4*)(aptrA + (kt + 3) * 16);
            rAb1 = *(const float4*)(aptrB + (kt + 3) * 16);
            rB1  = *(const float4*)(bptr + (size_t)(kt + 3) * 16 * ZZ);
        }
        // compute stage 1
        #pragma unroll
        for (int kc = 0; kc < 16; kc += 8) {
            unsigned a0[4], a1[4], bb[4][2];
            const float* A0 = SA[1] + (mB + gq) * 20 + kc + tq;
            a0[0] = __float_as_uint(A0[0]);      a0[1] = __float_as_uint(A0[8 * 20]);
            a0[2] = __float_as_uint(A0[4]);      a0[3] = __float_as_uint(A0[8 * 20 + 4]);
            const float* A1 = A0 + 16 * 20;
            a1[0] = __float_as_uint(A1[0]);      a1[1] = __float_as_uint(A1[8 * 20]);
            a1[2] = __float_as_uint(A1[4]);      a1[3] = __float_as_uint(A1[8 * 20 + 4]);
            const float* B0 = SB[1] + (kc + tq) * 72 + nB + gq;
            #pragma unroll
            for (int ns = 0; ns < 4; ns++) {
                bb[ns][0] = __float_as_uint(B0[ns * 8]);
                bb[ns][1] = __float_as_uint(B0[4 * 72 + ns * 8]);
            }
            #pragma unroll
            for (int ns = 0; ns < 4; ns++) { mma_tf32(d[0][ns], a0, bb[ns]); mma_tf32(d[1][ns], a1, bb[ns]); }
        }
        if (kt + 2 < 32) {
            *(float4*)&SA[0][ar * 20 + akq] = rAa0;
            *(float4*)&SA[0][(64 + ar) * 20 + akq] = rAb0;
            *(float4*)&SB[0][bkr * 72 + bnq] = rB0;
        }
        __syncthreads();
    }

    #pragma unroll
    for (int ms = 0; ms < 2; ms++) {
        #pragma unroll
        for (int ns = 0; ns < 4; ns++) {
            int r0 = rowBase + mB + ms * 16 + gq;
            int c0 = colBase + nB + ns * 8 + 2 * tq;
            int g0 = c0 & 3, u = c0 >> 2;
            float b0 = be[g0 * UU + u], b1 = be[(g0 + 1) * UU + u];
            float2 o1 = { d[ms][ns][0] + b0, d[ms][ns][1] + b1 };
            float2 o2 = { d[ms][ns][2] + b0, d[ms][ns][3] + b1 };
            *(float2*)&g_Zx[(size_t)r0 * ZZ + c0] = o1;
            *(float2*)&g_Zx[(size_t)(r0 + 8) * ZZ + c0] = o2;
        }
    }
}

// ---------------- persistent encoder: W-stationary h@Wh (K=512) + Zx epilogue ----------------
#define WS_FLOATS (512 * 72)
#define ESA_FLOATS (3 * 64 * 20)
#define SMEM_ENC_BYTES ((WS_FLOATS + ESA_FLOATS) * 4)

__global__ void __launch_bounds__(THR, 1) encoder_kernel() {
    extern __shared__ float es[];
    float* WS = es;                       // [512][72] resident Wh slice
    float* SA = es + WS_FLOATS;           // 3 stages of [64][20]

    const int tid = threadIdx.x, lane = tid & 31, wid = tid >> 5;
    const int rowBase = (blockIdx.x >> 5) << 6;
    const int colBase = (blockIdx.x & 31) << 6;
    const int mB = (wid >> 2) << 5;       // 0 / 32
    const int nB = (wid & 3) << 4;        // 0,16,32,48
    const int gq = lane >> 2, tq = lane & 3;
    const int arow = tid >> 2, akq = (tid & 3) << 2;

    // load resident Wh slice: 512 k x 64 n
    for (int j = tid; j < 512 * 16; j += THR) {
        int k = j >> 4, n4 = (j & 15) << 2;
        *(float4*)&WS[k * 72 + n4] = *(const float4*)&g_Whe[(size_t)k * ZZ + colBase + n4];
    }
    __syncthreads();

    unsigned gen = 0;
    for (int t = 0; t < TT; t++) {
        const float* A = g_Ah[t & 1];
        float* An = g_Ah[(t + 1) & 1];
        const float* aptr = A + (size_t)(rowBase + arow) * UU + akq;

        float4 rA0 = *(const float4*)(aptr);
        float4 rA1 = *(const float4*)(aptr + 16);
        *(float4*)&SA[0 * 1280 + arow * 20 + akq] = rA0;
        __syncthreads();

        float d[2][2][4];
        #pragma unroll
        for (int i = 0; i < 2; i++)
            #pragma unroll
            for (int j = 0; j < 2; j++)
                #pragma unroll
                for (int q = 0; q < 4; q++) d[i][j][q] = 0.f;

        #pragma unroll 1
        for (int kt = 0; kt < 32; kt += 2) {
            if (kt + 2 < 32) rA0 = *(const float4*)(aptr + (kt + 2) * 16);
            {   // stage kt
                const float* sa = &SA[(kt % 3) * 1280];
                const float* wsb = WS + (kt << 4) * 72;
                #pragma unroll
                for (int kc = 0; kc < 16; kc += 8) {
                    unsigned a0[4], a1[4], b0[2], b1[2];
                    const float* A0 = sa + (mB + gq) * 20 + kc + tq;
                    a0[0] = __float_as_uint(A0[0]);  a0[1] = __float_as_uint(A0[8 * 20]);
                    a0[2] = __float_as_uint(A0[4]);  a0[3] = __float_as_uint(A0[8 * 20 + 4]);
                    const float* A1 = A0 + 16 * 20;
                    a1[0] = __float_as_uint(A1[0]);  a1[1] = __float_as_uint(A1[8 * 20]);
                    a1[2] = __float_as_uint(A1[4]);  a1[3] = __float_as_uint(A1[8 * 20 + 4]);
                    const float* B0 = wsb + (kc + tq) * 72 + nB + gq;
                    b0[0] = __float_as_uint(B0[0]);  b0[1] = __float_as_uint(B0[4 * 72]);
                    b1[0] = __float_as_uint(B0[8]);  b1[1] = __float_as_uint(B0[4 * 72 + 8]);
                    mma_tf32(d[0][0], a0, b0); mma_tf32(d[0][1], a0, b1);
                    mma_tf32(d[1][0], a1, b0); mma_tf32(d[1][1], a1, b1);
                }
            }
            *(float4*)&SA[((kt + 1) % 3) * 1280 + arow * 20 + akq] = rA1;
            __syncthreads();

            if (kt + 3 < 32) rA1 = *(const float4*)(aptr + (kt + 3) * 16);
            {   // stage kt+1
                const float* sa = &SA[((kt + 1) % 3) * 1280];
                const float* wsb = WS + ((kt + 1) << 4) * 72;
                #pragma unroll
                for (int kc = 0; kc < 16; kc += 8) {
                    unsigned a0[4], a1[4], b0[2], b1[2];
                    const float* A0 = sa + (mB + gq) * 20 + kc + tq;
                    a0[0] = __float_as_uint(A0[0]);  a0[1] = __float_as_uint(A0[8 * 20]);
                    a0[2] = __float_as_uint(A0[4]);  a0[3] = __float_as_uint(A0[8 * 20 + 4]);
                    const float* A1 = A0 + 16 * 20;
                    a1[0] = __float_as_uint(A1[0]);  a1[1] = __float_as_uint(A1[8 * 20]);
                    a1[2] = __float_as_uint(A1[4]);  a1[3] = __float_as_uint(A1[8 * 20 + 4]);
                    const float* B0 = wsb + (kc + tq) * 72 + nB + gq;
                    b0[0] = __float_as_uint(B0[0]);  b0[1] = __float_as_uint(B0[4 * 72]);
                    b1[0] = __float_as_uint(B0[8]);  b1[1] = __float_as_uint(B0[4 * 72 + 8]);
                    mma_tf32(d[0][0], a0, b0); mma_tf32(d[0][1], a0, b1);
                    mma_tf32(d[1][0], a1, b0); mma_tf32(d[1][1], a1, b1);
                }
            }
            if (kt + 2 < 32)
                *(float4*)&SA[((kt + 2) % 3) * 1280 + arow * 20 + akq] = rA0;
            __syncthreads();
        }

        // epilogue: z = d + Zx[t] (bias folded in Zx), gates, state update
        #pragma unroll
        for (int ms = 0; ms < 2; ms++) {
            #pragma unroll
            for (int ns = 0; ns < 2; ns++) {
                int r0 = rowBase + mB + ms * 16 + gq;
                int c0 = colBase + nB + ns * 8 + 2 * tq;
                const float* zx = &g_Zx[((size_t)t * BB + r0) * ZZ + c0];
                float2 zxa = *(const float2*)zx;
                float2 zxb = *(const float2*)(zx + (size_t)8 * ZZ);
                float z0 = d[ms][ns][0] + zxa.x;
                float z1 = d[ms][ns][1] + zxa.y;
                float z2 = d[ms][ns][2] + zxb.x;
                float z3 = d[ms][ns][3] + zxb.y;
                float p0 = __shfl_xor_sync(0xffffffffu, z0, 1);
                float p1 = __shfl_xor_sync(0xffffffffu, z1, 1);
                float p2 = __shfl_xor_sync(0xffffffffu, z2, 1);
                float p3 = __shfl_xor_sync(0xffffffffu, z3, 1);
                if (!(tq & 1)) {
                    int u = c0 >> 2;
                    #pragma unroll
                    for (int rr = 0; rr < 2; rr++) {
                        int b = r0 + rr * 8;
                        float zi = rr ? z2 : z0, zf = rr ? z3 : z1;
                        float zg = rr ? p2 : p0, zo = rr ? p3 : p1;
                        int idx = b * UU + u;
                        float c = sigf(zf) * g_c[idx] + sigf(zi) * tanhx(zg);
                        float h = sigf(zo) * tanhx(c);
                        g_c[idx] = c;
                        An[idx] = tf32r(h);
                        g_encH[((size_t)b * TT + t) * UU + u] = __float2half_rn(h);
                        if (t == TT - 1) g_h[idx] = h;
                    }
                }
            }
        }
        gsync(++gen);
    }
}

// ---------------- decoder GEMM (streaming W, K=1024) + fused gates ----------------
struct SmemGemm {
    float SA[2][64 * 20];
    float SB[2][16 * 72];
};

__device__ __forceinline__ void compute_stage(const float* __restrict__ sA,
                                              const float* __restrict__ sB,
                                              int mB, int nB, int gq, int tq,
                                              float d[2][2][4]) {
    #pragma unroll
    for (int kc = 0; kc < 16; kc += 8) {
        unsigned a0[4], a1[4], b0[2], b1[2];
        const float* A0 = sA + (mB + gq) * 20 + kc + tq;
        a0[0] = __float_as_uint(A0[0]);
        a0[1] = __float_as_uint(A0[8 * 20]);
        a0[2] = __float_as_uint(A0[4]);
        a0[3] = __float_as_uint(A0[8 * 20 + 4]);
        const float* A1 = A0 + 16 * 20;
        a1[0] = __float_as_uint(A1[0]);
        a1[1] = __float_as_uint(A1[8 * 20]);
        a1[2] = __float_as_uint(A1[4]);
        a1[3] = __float_as_uint(A1[8 * 20 + 4]);
        const float* B0 = sB + (kc + tq) * 72 + nB + gq;
        b0[0] = __float_as_uint(B0[0]);
        b0[1] = __float_as_uint(B0[4 * 72]);
        b1[0] = __float_as_uint(B0[8]);
        b1[1] = __float_as_uint(B0[4 * 72 + 8]);
        mma_tf32(d[0][0], a0, b0);
        mma_tf32(d[0][1], a0, b1);
        mma_tf32(d[1][0], a1, b0);
        mma_tf32(d[1][1], a1, b1);
    }
}

__device__ __forceinline__ void dec_lstm_step(const float* __restrict__ Acur,
                                              float* __restrict__ Anext,
                                              SmemGemm& sm) {
    const int tid = threadIdx.x;
    const int lane = tid & 31, wid = tid >> 5;
    const int rowBase = (blockIdx.x >> 5) << 6;
    const int colBase = (blockIdx.x & 31) << 6;
    const int mB = (wid >> 2) << 5;
    const int nB = (wid & 3) << 4;
    const int gq = lane >> 2, tq = lane & 3;

    const int arow = tid >> 2;
    const int akq  = (tid & 3) << 2;
    const int bkr  = tid >> 4;
    const int bnq  = (tid & 15) << 2;

    const float* aptr = Acur + (size_t)(rowBase + arow) * KK + akq;
    const float* bptr = g_Wdec + (size_t)bkr * ZZ + colBase + bnq;

    float4 ra0 = *(const float4*)(aptr);
    float4 rb0 = *(const float4*)(bptr);
    float4 ra1 = *(const float4*)(aptr + 16);
    float4 rb1 = *(const float4*)(bptr + (size_t)16 * ZZ);
    *(float4*)&sm.SA[0][arow * 20 + akq] = ra0;
    *(float4*)&sm.SB[0][bkr * 72 + bnq] = rb0;
    __syncthreads();

    float d[2][2][4];
    #pragma unroll
    for (int i = 0; i < 2; i++)
        #pragma unroll
        for (int j = 0; j < 2; j++)
            #pragma unroll
            for (int q = 0; q < 4; q++) d[i][j][q] = 0.f;

    #pragma unroll 1
    for (int kt = 0; kt < 64; kt += 2) {
        if (kt + 2 < 64) {
            ra0 = *(const float4*)(aptr + (kt + 2) * 16);
            rb0 = *(const float4*)(bptr + (size_t)(kt + 2) * 16 * ZZ);
        }
        compute_stage(sm.SA[0], sm.SB[0], mB, nB, gq, tq, d);
        *(float4*)&sm.SA[1][arow * 20 + akq] = ra1;
        *(float4*)&sm.SB[1][bkr * 72 + bnq] = rb1;
        __syncthreads();

        if (kt + 3 < 64) {
            ra1 = *(const float4*)(aptr + (kt + 3) * 16);
            rb1 = *(const float4*)(bptr + (size_t)(kt + 3) * 16 * ZZ);
        }
        compute_stage(sm.SA[1], sm.SB[1], mB, nB, gq, tq, d);
        if (kt + 2 < 64) {
            *(float4*)&sm.SA[0][arow * 20 + akq] = ra0;
            *(float4*)&sm.SB[0][bkr * 72 + bnq] = rb0;
        }
        __syncthreads();
    }

    #pragma unroll
    for (int ms = 0; ms < 2; ms++) {
        #pragma unroll
        for (int ns = 0; ns < 2; ns++) {
            int c0 = colBase + nB + ns * 8 + 2 * tq;
            float bv0 = g_Bdec[c0], bv1 = g_Bdec[c0 + 1];
            float z0 = d[ms][ns][0] + bv0;
            float z1 = d[ms][ns][1] + bv1;
            float z2 = d[ms][ns][2] + bv0;
            float z3 = d[ms][ns][3] + bv1;
            float p0 = __shfl_xor_sync(0xffffffffu, z0, 1);
            float p1 = __shfl_xor_sync(0xffffffffu, z1, 1);
            float p2 = __shfl_xor_sync(0xffffffffu, z2, 1);
            float p3 = __shfl_xor_sync(0xffffffffu, z3, 1);
            if (!(tq & 1)) {
                int u = c0 >> 2;
                int r0 = rowBase + mB + ms * 16 + gq;
                #pragma unroll
                for (int rr = 0; rr < 2; rr++) {
                    int b = r0 + rr * 8;
                    float zi = rr ? z2 : z0, zf = rr ? z3 : z1;
                    float zg = rr ? p2 : p0, zo = rr ? p3 : p1;
                    int idx = b * UU + u;
                    float c = sigf(zf) * g_c[idx] + sigf(zi) * tanhx(zg);
                    float h = sigf(zo) * tanhx(c);
                    g_c[idx] = c;
                    g_h[idx] = h;
                    Anext[b * KK + UU + u] = tf32r(h);
                }
            }
        }
    }
}

// ---------------- persistent decoder ----------------
struct SmemDec {
    SmemGemm g;
    float wctx[8][UU];
    float sc[TT];
    float wm[8];
    float wz[8];
};

__global__ void __launch_bounds__(THR, 1) decoder_kernel(
    const float* __restrict__ ptr_w, const float* __restrict__ ptr_b,
    float* __restrict__ out) {
    __shared__ SmemDec sm;
    unsigned gen = TT;

    // prologue: A[0] = [x0 | tf32(h_enc_final)]
    {
        int base = blockIdx.x * (BB * UU / GRID) + threadIdx.x;
        #pragma unroll
        for (int i = 0; i < (BB * UU / GRID) / THR; i++) {
            int idx = base + i * THR;
            int b = idx >> 9, u = idx & 511;
            g_Ad[0][b * KK + u] = g_x0[idx];
            g_Ad[0][b * KK + UU + u] = tf32r(g_h[idx]);
        }
    }
    gsync(++gen);

    const float w  = *ptr_w;
    const float pb = *ptr_b;
    const int tid = threadIdx.x, lane = tid & 31, warp = tid >> 5;

    for (int s = 0; s < TT; s++) {
        dec_lstm_step(g_Ad[s & 1], g_Ad[(s + 1) & 1], sm.g);
        gsync(++gen);
        float* Anext = g_Ad[(s + 1) & 1];

        // online-softmax attention over fp16 enc; 2 batch rows per CTA
        for (int rb = 0; rb < 2; rb++) {
            const int b = blockIdx.x * 2 + rb;
            float hx[16];
            {
                const float4* hb = (const float4*)&g_h[b * UU];
                float4 q0 = hb[2 * lane], q1 = hb[2 * lane + 1];
                float4 q2 = hb[2 * lane + 64], q3 = hb[2 * lane + 65];
                hx[0]=q0.x; hx[1]=q0.y; hx[2]=q0.z; hx[3]=q0.w;
                hx[4]=q1.x; hx[5]=q1.y; hx[6]=q1.z; hx[7]=q1.w;
                hx[8]=q2.x; hx[9]=q2.y; hx[10]=q2.z; hx[11]=q2.w;
                hx[12]=q3.x; hx[13]=q3.y; hx[14]=q3.z; hx[15]=q3.w;
            }
            float ca[16];
            #pragma unroll
            for (int j = 0; j < 16; j++) ca[j] = 0.f;
            float m = -3.0e38f, Zw = 0.f;

            for (int t = warp; t < TT; t += 8) {
                const uint4* ep = (const uint4*)&g_encH[((size_t)b * TT + t) * UU];
                uint4 E0 = ep[lane], E1 = ep[lane + 32];
                float ex[16];
                h2f(E0.x, ex[0], ex[1]);  h2f(E0.y, ex[2], ex[3]);
                h2f(E0.z, ex[4], ex[5]);  h2f(E0.w, ex[6], ex[7]);
                h2f(E1.x, ex[8], ex[9]);  h2f(E1.y, ex[10], ex[11]);
                h2f(E1.z, ex[12], ex[13]); h2f(E1.w, ex[14], ex[15]);
                float sd = 0.f;
                #pragma unroll
                for (int j = 0; j < 16; j++) sd = fmaf(ex[j], hx[j], sd);
                #pragma unroll
                for (int o = 16; o; o >>= 1) sd += __shfl_xor_sync(0xffffffffu, sd, o);
                float sv = sd * w + pb;
                if (lane == 0) sm.sc[t] = sv;
                float mn = fmaxf(m, sv);
                float scale = __expf(m - mn);
                float es = __expf(sv - mn);
                Zw = Zw * scale + es;
                #pragma unroll
                for (int j = 0; j < 16; j++) ca[j] = ca[j] * scale + es * ex[j];
                m = mn;
            }
            if (lane == 0) { sm.wm[warp] = m; sm.wz[warp] = Zw; }
            {
                float4* wc = (float4*)sm.wctx[warp];
                wc[2 * lane]      = make_float4(ca[0], ca[1], ca[2], ca[3]);
                wc[2 * lane + 1]  = make_float4(ca[4], ca[5], ca[6], ca[7]);
                wc[2 * lane + 64] = make_float4(ca[8], ca[9], ca[10], ca[11]);
                wc[2 * lane + 65] = make_float4(ca[12], ca[13], ca[14], ca[15]);
            }
            __syncthreads();

            float M = sm.wm[0];
            #pragma unroll
            for (int q = 1; q < 8; q++) M = fmaxf(M, sm.wm[q]);
            float Zt = 0.f, x0a = 0.f, x1a = 0.f;
            #pragma unroll
            for (int q = 0; q < 8; q++) {
                float e = __expf(sm.wm[q] - M);
                Zt += e * sm.wz[q];
                x0a += e * sm.wctx[q][tid];
                x1a += e * sm.wctx[q][tid + 256];
            }
            float invZ = 1.0f / Zt;
            Anext[b * KK + tid]       = tf32r(x0a * invZ);
            Anext[b * KK + 256 + tid] = tf32r(x1a * invZ);
            out[(size_t)b * (TT * TT) + (size_t)s * TT + tid] = __expf(sm.sc[tid] - M) * invZ;
            __syncthreads();
        }
        gsync(++gen);
    }
}

// ---------------- launch ----------------
extern "C" void kernel_launch(void* const* d_in, const int* in_sizes, int n_in,
                              void* d_out, int out_size) {
    const float* inputs = (const float*)d_in[0];
    const float* score  = (const float*)d_in[1];
    const float* enc_Wx = (const float*)d_in[2];
    const float* enc_Wh = (const float*)d_in[3];
    const float* enc_b  = (const float*)d_in[4];
    const float* dec_Wx = (const float*)d_in[5];
    const float* dec_Wh = (const float*)d_in[6];
    const float* dec_b  = (const float*)d_in[7];
    const float* ptr_w  = (const float*)d_in[8];
    const float* ptr_b  = (const float*)d_in[9];
    float* out = (float*)d_out;

    cudaFuncSetAttribute(encoder_kernel, cudaFuncAttributeMaxDynamicSharedMemorySize,
                         SMEM_ENC_BYTES);

    prep_w_enc<<<(UU * ZZ + THR - 1) / THR, THR>>>(enc_Wx, enc_Wh);
    prep_w_dec<<<(KK * ZZ + THR - 1) / THR, THR>>>(dec_Wx, dec_Wh);
    prep_bias_kernel<<<(ZZ + THR - 1) / THR, THR>>>(dec_b);
    prep_x_kernel<<<(int)(((size_t)TT * BB * UU + THR - 1) / THR), THR>>>(inputs, score);
    mean_kernel<<<(BB * UU + THR - 1) / THR, THR>>>();
    init_kernel<<<(BB * UU + THR - 1) / THR, THR>>>();

    dim3 zgrid(ZZ / 64, (TT * BB) / 128);   // (32, 512)
    zx_kernel<<<zgrid, 256>>>(enc_b);

    encoder_kernel<<<GRID, THR, SMEM_ENC_BYTES>>>();
    decoder_kernel<<<GRID, THR>>>(ptr_w, ptr_b, out);
}

// round 5
// speedup vs baseline: 4.2067x; 1.2499x over previous
#include <cuda_runtime.h>
#include <cuda_fp16.h>
#include <math.h>

#define BB 256       // batch
#define TT 256       // timesteps
#define FF 511       // raw feature dim
#define UU 512       // units
#define ZZ 2048      // 4*U (gate-interleaved cols: n' = 4u + gate)
#define KK 1024      // decoder fused K
#define GRID 128
#define THR 256
#define AST 40       // A smem stage stride (halfs)

// ---------------- device scratch ----------------
__device__ float  g_Xt[(size_t)TT * BB * UU];    // [t][b][u] tf32 input (score appended)
__device__ float  g_Zx[(size_t)TT * BB * ZZ];    // x@Wx + bias (gate-interleaved), fp32
__device__ __half g_encH[(size_t)BB * TT * UU];  // [b][t][u] encoder hidden, fp16
__device__ float  g_Wxe[(size_t)UU * ZZ];        // enc Wx interleaved, tf32 (for zx GEMM)
__device__ __half g_WheT[(size_t)ZZ * UU];       // enc Wh, [n'][k] n-major, fp16
__device__ __half g_WdT[(size_t)ZZ * KK];        // dec [Wx;Wh], [n'][k] n-major, fp16
__device__ float  g_Bdec[ZZ];
__device__ __half g_AhH[2][BB * UU];             // encoder h operand, fp16
__device__ __half g_AdH[2][BB * KK];             // decoder [xin|h] operand, fp16
__device__ float  g_h[BB * UU];                  // fp32 h for attention
__device__ float  g_c[BB * UU];
__device__ float  g_x0[BB * UU];
__device__ unsigned g_cnt, g_gen;

// ---------------- helpers ----------------
__device__ __forceinline__ float tf32r(float x) {
    unsigned r; asm("cvt.rna.tf32.f32 %0, %1;" : "=r"(r) : "f"(x));
    return __uint_as_float(r);
}
__device__ __forceinline__ float sigf(float x) { return 1.0f / (1.0f + __expf(-x)); }
__device__ __forceinline__ float tanhx(float x) { return 2.0f / (1.0f + __expf(-2.0f * x)) - 1.0f; }
__device__ __forceinline__ void h2f(unsigned v, float& a, float& b) {
    float2 f = __half22float2(*reinterpret_cast<const __half2*>(&v));
    a = f.x; b = f.y;
}
__device__ __forceinline__ void cvt16(const uint4 E[2], float ex[16]) {
    h2f(E[0].x, ex[0], ex[1]);   h2f(E[0].y, ex[2], ex[3]);
    h2f(E[0].z, ex[4], ex[5]);   h2f(E[0].w, ex[6], ex[7]);
    h2f(E[1].x, ex[8], ex[9]);   h2f(E[1].y, ex[10], ex[11]);
    h2f(E[1].z, ex[12], ex[13]); h2f(E[1].w, ex[14], ex[15]);
}

// cheap grid barrier: atomic arrive, volatile-load poll (no RMW storm)
__device__ __forceinline__ void gsync(unsigned target) {
    __syncthreads();
    if (threadIdx.x == 0) {
        __threadfence();
        if (atomicAdd(&g_cnt, 1u) == GRID - 1u) {
            g_cnt = 0u;
            __threadfence();
            *(volatile unsigned*)&g_gen = target;
        } else {
            while (*(volatile unsigned*)&g_gen < target) __nanosleep(20);
            __threadfence();
        }
    }
    __syncthreads();
}

__device__ __forceinline__ void mma_tf32(float d[4], const unsigned a[4], const unsigned b[2]) {
    asm volatile("mma.sync.aligned.m16n8k8.row.col.f32.tf32.tf32.f32 "
                 "{%0,%1,%2,%3}, {%4,%5,%6,%7}, {%8,%9}, {%0,%1,%2,%3};\n"
                 : "+f"(d[0]), "+f"(d[1]), "+f"(d[2]), "+f"(d[3])
                 : "r"(a[0]), "r"(a[1]), "r"(a[2]), "r"(a[3]), "r"(b[0]), "r"(b[1]));
}
__device__ __forceinline__ void mma_f16(float d[4], const unsigned a[4], const unsigned b[2]) {
    asm volatile("mma.sync.aligned.m16n8k16.row.col.f32.f16.f16.f32 "
                 "{%0,%1,%2,%3}, {%4,%5,%6,%7}, {%8,%9}, {%0,%1,%2,%3};\n"
                 : "+f"(d[0]), "+f"(d[1]), "+f"(d[2]), "+f"(d[3])
                 : "r"(a[0]), "r"(a[1]), "r"(a[2]), "r"(a[3]), "r"(b[0]), "r"(b[1]));
}

// ---------------- prep kernels ----------------
__global__ void prep_x_kernel(const float* __restrict__ inputs, const float* __restrict__ score) {
    size_t idx = (size_t)blockIdx.x * blockDim.x + threadIdx.x;
    if (idx >= (size_t)TT * BB * UU) return;
    int t = (int)(idx / (BB * UU));
    int rem = (int)(idx % (BB * UU));
    int b = rem / UU, u = rem % UU;
    float v = (u < FF) ? inputs[((size_t)b * TT + t) * FF + u] : score[b];
    g_Xt[idx] = tf32r(v);
}

__global__ void mean_kernel() {
    int idx = blockIdx.x * blockDim.x + threadIdx.x;
    if (idx >= BB * UU) return;
    float s = 0.f;
    #pragma unroll 4
    for (int t = 0; t < TT; t++) s += g_Xt[(size_t)t * (BB * UU) + idx];
    g_x0[idx] = s * (1.0f / TT);
}

__global__ void prep_w_enc(const float* __restrict__ Wx, const float* __restrict__ Wh) {
    size_t idx = (size_t)blockIdx.x * blockDim.x + threadIdx.x;
    if (idx >= (size_t)UU * ZZ) return;
    int k = (int)(idx / ZZ), np = (int)(idx % ZZ);
    int n = (np & 3) * UU + (np >> 2);
    g_Wxe[idx] = tf32r(Wx[(size_t)k * ZZ + n]);
    g_WheT[(size_t)np * UU + k] = __float2half_rn(Wh[(size_t)k * ZZ + n]);
}

__global__ void prep_w_dec(const float* __restrict__ Wx, const float* __restrict__ Wh) {
    size_t idx = (size_t)blockIdx.x * blockDim.x + threadIdx.x;
    if (idx >= (size_t)KK * ZZ) return;
    int k = (int)(idx / ZZ), np = (int)(idx % ZZ);
    int n = (np & 3) * UU + (np >> 2);
    float v = (k < UU) ? Wx[(size_t)k * ZZ + n] : Wh[(size_t)(k - UU) * ZZ + n];
    g_WdT[(size_t)np * KK + k] = __float2half_rn(v);
}

__global__ void prep_bias_kernel(const float* __restrict__ bd) {
    int np = blockIdx.x * blockDim.x + threadIdx.x;
    if (np >= ZZ) return;
    g_Bdec[np] = bd[(np & 3) * UU + (np >> 2)];
}

__global__ void init_kernel() {
    int idx = blockIdx.x * blockDim.x + threadIdx.x;
    if (idx == 0) { g_cnt = 0u; g_gen = 0u; }
    if (idx >= BB * UU) return;
    g_AhH[0][idx] = __float2half_rn(0.f);
    g_c[idx] = 0.f;
}

// ---------------- Zx = X @ Wxe + bias : big parallel tf32 GEMM (unchanged R4) ----------------
__global__ void __launch_bounds__(256) zx_kernel(const float* __restrict__ be) {
    __shared__ float SAx[2][128 * 20];
    __shared__ float SBx[2][16 * 72];
    const int tid = threadIdx.x, lane = tid & 31, wid = tid >> 5;
    const int rowBase = blockIdx.y << 7;
    const int colBase = blockIdx.x << 6;
    const int mB = (wid >> 1) << 5;
    const int nB = (wid & 1) << 5;
    const int gq = lane >> 2, tq = lane & 3;

    const int ar = tid >> 2;
    const int akq = (tid & 3) << 2;
    const int bkr = tid >> 4, bnq = (tid & 15) << 2;
    const float* aptrA = g_Xt + (size_t)(rowBase + ar) * UU + akq;
    const float* aptrB = aptrA + (size_t)64 * UU;
    const float* bptr = g_Wxe + (size_t)bkr * ZZ + colBase + bnq;

    float4 rAa0 = *(const float4*)(aptrA);
    float4 rAb0 = *(const float4*)(aptrB);
    float4 rB0  = *(const float4*)(bptr);
    float4 rAa1 = *(const float4*)(aptrA + 16);
    float4 rAb1 = *(const float4*)(aptrB + 16);
    float4 rB1  = *(const float4*)(bptr + (size_t)16 * ZZ);
    *(float4*)&SAx[0][ar * 20 + akq] = rAa0;
    *(float4*)&SAx[0][(64 + ar) * 20 + akq] = rAb0;
    *(float4*)&SBx[0][bkr * 72 + bnq] = rB0;
    __syncthreads();

    float d[2][4][4];
    #pragma unroll
    for (int i = 0; i < 2; i++)
        #pragma unroll
        for (int j = 0; j < 4; j++)
            #pragma unroll
            for (int q = 0; q < 4; q++) d[i][j][q] = 0.f;

    #pragma unroll 1
    for (int kt = 0; kt < 32; kt += 2) {
        if (kt + 2 < 32) {
            rAa0 = *(const float4*)(aptrA + (kt + 2) * 16);
            rAb0 = *(const float4*)(aptrB + (kt + 2) * 16);
            rB0  = *(const float4*)(bptr + (size_t)(kt + 2) * 16 * ZZ);
        }
        #pragma unroll
        for (int kc = 0; kc < 16; kc += 8) {
            unsigned a0[4], a1[4], bbf[4][2];
            const float* A0 = SAx[0] + (mB + gq) * 20 + kc + tq;
            a0[0] = __float_as_uint(A0[0]);      a0[1] = __float_as_uint(A0[8 * 20]);
            a0[2] = __float_as_uint(A0[4]);      a0[3] = __float_as_uint(A0[8 * 20 + 4]);
            const float* A1 = A0 + 16 * 20;
            a1[0] = __float_as_uint(A1[0]);      a1[1] = __float_as_uint(A1[8 * 20]);
            a1[2] = __float_as_uint(A1[4]);      a1[3] = __float_as_uint(A1[8 * 20 + 4]);
            const float* B0 = SBx[0] + (kc + tq) * 72 + nB + gq;
            #pragma unroll
            for (int ns = 0; ns < 4; ns++) {
                bbf[ns][0] = __float_as_uint(B0[ns * 8]);
                bbf[ns][1] = __float_as_uint(B0[4 * 72 + ns * 8]);
            }
            #pragma unroll
            for (int ns = 0; ns < 4; ns++) { mma_tf32(d[0][ns], a0, bbf[ns]); mma_tf32(d[1][ns], a1, bbf[ns]); }
        }
        *(float4*)&SAx[1][ar * 20 + akq] = rAa1;
        *(float4*)&SAx[1][(64 + ar) * 20 + akq] = rAb1;
        *(float4*)&SBx[1][bkr * 72 + bnq] = rB1;
        __syncthreads();

        if (kt + 3 < 32) {
            rAa1 = *(const float4*)(aptrA + (kt + 3) * 16);
            rAb1 = *(const float4*)(aptrB + (kt + 3) * 16);
            rB1  = *(const float4*)(bptr + (size_t)(kt + 3) * 16 * ZZ);
        }
        #pragma unroll
        for (int kc = 0; kc < 16; kc += 8) {
            unsigned a0[4], a1[4], bbf[4][2];
            const float* A0 = SAx[1] + (mB + gq) * 20 + kc + tq;
            a0[0] = __float_as_uint(A0[0]);      a0[1] = __float_as_uint(A0[8 * 20]);
            a0[2] = __float_as_uint(A0[4]);      a0[3] = __float_as_uint(A0[8 * 20 + 4]);
            const float* A1 = A0 + 16 * 20;
            a1[0] = __float_as_uint(A1[0]);      a1[1] = __float_as_uint(A1[8 * 20]);
            a1[2] = __float_as_uint(A1[4]);      a1[3] = __float_as_uint(A1[8 * 20 + 4]);
            const float* B0 = SBx[1] + (kc + tq) * 72 + nB + gq;
            #pragma unroll
            for (int ns = 0; ns < 4; ns++) {
                bbf[ns][0] = __float_as_uint(B0[ns * 8]);
                bbf[ns][1] = __float_as_uint(B0[4 * 72 + ns * 8]);
            }
            #pragma unroll
            for (int ns = 0; ns < 4; ns++) { mma_tf32(d[0][ns], a0, bbf[ns]); mma_tf32(d[1][ns], a1, bbf[ns]); }
        }
        if (kt + 2 < 32) {
            *(float4*)&SAx[0][ar * 20 + akq] = rAa0;
            *(float4*)&SAx[0][(64 + ar) * 20 + akq] = rAb0;
            *(float4*)&SBx[0][bkr * 72 + bnq] = rB0;
        }
        __syncthreads();
    }

    #pragma unroll
    for (int ms = 0; ms < 2; ms++) {
        #pragma unroll
        for (int ns = 0; ns < 4; ns++) {
            int r0 = rowBase + mB + ms * 16 + gq;
            int c0 = colBase + nB + ns * 8 + 2 * tq;
            int g0 = c0 & 3, u = c0 >> 2;
            float b0 = be[g0 * UU + u], b1 = be[(g0 + 1) * UU + u];
            float2 o1 = { d[ms][ns][0] + b0, d[ms][ns][1] + b1 };
            float2 o2 = { d[ms][ns][2] + b0, d[ms][ns][3] + b1 };
            *(float2*)&g_Zx[(size_t)r0 * ZZ + c0] = o1;
            *(float2*)&g_Zx[(size_t)(r0 + 8) * ZZ + c0] = o2;
        }
    }
}

// ---------------- fp16 W-stationary GEMM mainloop ----------------
// CTA tile 64x64, 8 warps 2(M)x4(N), warp tile 32x16, mma m16n8k16.
// WS: resident W slice in smem [64 n][KD+8 halfs]; SA: 3 stages [64 m][AST halfs].
template<int KD>
__device__ __forceinline__ void gemm_f16_loop(const __half* __restrict__ Acta,
                                              const __half* __restrict__ WS,
                                              __half* __restrict__ SA,
                                              float d[2][2][4]) {
    const int tid = threadIdx.x, lane = tid & 31, wid = tid >> 5;
    const int mB = (wid >> 2) << 5;
    const int nB = (wid & 3) << 4;
    const int gq = lane >> 2, tq = lane & 3;
    const int r = tid >> 2, j8 = (tid & 3) << 3;
    const int WSTR = KD + 8;
    const __half* ap = Acta + (size_t)r * KD + j8;

    uint4 p0 = *(const uint4*)(ap);
    uint4 p1 = *(const uint4*)(ap + 32);
    *(uint4*)&SA[r * AST + j8] = p0;
    __syncthreads();

    constexpr int S = KD / 32;
    #pragma unroll 1
    for (int s = 0; s < S; s++) {
        uint4 nxt;
        if (s + 2 < S) nxt = *(const uint4*)(ap + (s + 2) * 32);
        if (s + 1 < S) *(uint4*)&SA[((s + 1) % 3) * (64 * AST) + r * AST + j8] = p1;

        const __half* sa = SA + (s % 3) * (64 * AST);
        const int kb = s << 5;
        #pragma unroll
        for (int kc = 0; kc < 32; kc += 16) {
            unsigned a0[4], a1[4], b0[2], b1[2];
            const __half* A0 = sa + (mB + gq) * AST + kc + 2 * tq;
            a0[0] = *(const unsigned*)(A0);
            a0[1] = *(const unsigned*)(A0 + 8 * AST);
            a0[2] = *(const unsigned*)(A0 + 8);
            a0[3] = *(const unsigned*)(A0 + 8 * AST + 8);
            const __half* A1 = A0 + 16 * AST;
            a1[0] = *(const unsigned*)(A1);
            a1[1] = *(const unsigned*)(A1 + 8 * AST);
            a1[2] = *(const unsigned*)(A1 + 8);
            a1[3] = *(const unsigned*)(A1 + 8 * AST + 8);
            const __half* B0 = WS + (nB + gq) * WSTR + kb + kc + 2 * tq;
            b0[0] = *(const unsigned*)(B0);
            b0[1] = *(const unsigned*)(B0 + 8);
            const __half* B1 = B0 + 8 * WSTR;
            b1[0] = *(const unsigned*)(B1);
            b1[1] = *(const unsigned*)(B1 + 8);
            mma_f16(d[0][0], a0, b0);
            mma_f16(d[0][1], a0, b1);
            mma_f16(d[1][0], a1, b0);
            mma_f16(d[1][1], a1, b1);
        }
        __syncthreads();
        p1 = nxt;
    }
}

// ---------------- persistent encoder ----------------
#define ENC_WS_H (64 * (UU + 8))
#define ENC_SMEM ((ENC_WS_H + 3 * 64 * AST) * 2)

__global__ void __launch_bounds__(THR, 1) encoder_kernel() {
    extern __shared__ __half es[];
    __half* WS = es;
    __half* SA = es + ENC_WS_H;

    const int tid = threadIdx.x, lane = tid & 31, wid = tid >> 5;
    const int rowBase = (blockIdx.x >> 5) << 6;
    const int colBase = (blockIdx.x & 31) << 6;
    const int mB = (wid >> 2) << 5;
    const int nB = (wid & 3) << 4;
    const int gq = lane >> 2, tq = lane & 3;

    // load resident Wh slice [64 n][512 k]
    for (int j = tid; j < 64 * 64; j += THR) {
        int row = j >> 6, ch = (j & 63) << 3;
        *(uint4*)&WS[row * (UU + 8) + ch] =
            *(const uint4*)&g_WheT[(size_t)(colBase + row) * UU + ch];
    }
    __syncthreads();

    unsigned gen = 0;
    for (int t = 0; t < TT; t++) {
        const __half* Acta = g_AhH[t & 1] + (size_t)rowBase * UU;
        __half* An = g_AhH[(t + 1) & 1];

        float d[2][2][4];
        #pragma unroll
        for (int i = 0; i < 2; i++)
            #pragma unroll
            for (int j = 0; j < 2; j++)
                #pragma unroll
                for (int q = 0; q < 4; q++) d[i][j][q] = 0.f;

        gemm_f16_loop<UU>(Acta, WS, SA, d);

        // epilogue: z = d + Zx[t], gates, state update
        #pragma unroll
        for (int ms = 0; ms < 2; ms++) {
            #pragma unroll
            for (int ns = 0; ns < 2; ns++) {
                int r0 = rowBase + mB + ms * 16 + gq;
                int c0 = colBase + nB + ns * 8 + 2 * tq;
                const float* zx = &g_Zx[((size_t)t * BB + r0) * ZZ + c0];
                float2 zxa = *(const float2*)zx;
                float2 zxb = *(const float2*)(zx + (size_t)8 * ZZ);
                float z0 = d[ms][ns][0] + zxa.x;
                float z1 = d[ms][ns][1] + zxa.y;
                float z2 = d[ms][ns][2] + zxb.x;
                float z3 = d[ms][ns][3] + zxb.y;
                float p0 = __shfl_xor_sync(0xffffffffu, z0, 1);
                float p1 = __shfl_xor_sync(0xffffffffu, z1, 1);
                float p2 = __shfl_xor_sync(0xffffffffu, z2, 1);
                float p3 = __shfl_xor_sync(0xffffffffu, z3, 1);
                if (!(tq & 1)) {
                    int u = c0 >> 2;
                    #pragma unroll
                    for (int rr = 0; rr < 2; rr++) {
                        int b = r0 + rr * 8;
                        float zi = rr ? z2 : z0, zf = rr ? z3 : z1;
                        float zg = rr ? p2 : p0, zo = rr ? p3 : p1;
                        int idx = b * UU + u;
                        float c = sigf(zf) * g_c[idx] + sigf(zi) * tanhx(zg);
                        float h = sigf(zo) * tanhx(c);
                        g_c[idx] = c;
                        __half hh = __float2half_rn(h);
                        An[idx] = hh;
                        g_encH[((size_t)b * TT + t) * UU + u] = hh;
                    }
                }
            }
        }
        gsync(++gen);
    }
}

// ---------------- persistent decoder ----------------
#define DEC_WS_H (64 * (KK + 8))
#define DEC_SA_H (3 * 64 * AST)
#define DEC_SMEM (DEC_WS_H * 2 + DEC_SA_H * 2 + (8 * UU + 2 * TT + 16) * 4)

__global__ void __launch_bounds__(THR, 1) decoder_kernel(
    const float* __restrict__ ptr_w, const float* __restrict__ ptr_b,
    float* __restrict__ out) {
    extern __shared__ __half ds[];
    __half* WS = ds;
    __half* SA = ds + DEC_WS_H;
    float* wctx = (float*)(ds + DEC_WS_H + DEC_SA_H);   // [8][512]
    float* sc   = wctx + 8 * UU;                        // [2][256]
    float* wm   = sc + 2 * TT;                          // [8]
    float* wz   = wm + 8;                               // [8]

    const int tid = threadIdx.x, lane = tid & 31, warp = tid >> 5;
    const int rowBase = (blockIdx.x >> 5) << 6;
    const int colBase = (blockIdx.x & 31) << 6;
    const int mB = (warp >> 2) << 5;
    const int nB = (warp & 3) << 4;
    const int gq = lane >> 2, tq = lane & 3;

    // load resident Wdec slice [64 n][1024 k]
    for (int j = tid; j < 64 * 128; j += THR) {
        int row = j >> 7, ch = (j & 127) << 3;
        *(uint4*)&WS[row * (KK + 8) + ch] =
            *(const uint4*)&g_WdT[(size_t)(colBase + row) * KK + ch];
    }

    // prologue: A[0] = [x0 | h_enc_final]
    {
        int base = blockIdx.x * (BB * UU / GRID) + tid;
        #pragma unroll
        for (int i = 0; i < (BB * UU / GRID) / THR; i++) {
            int idx = base + i * THR;
            int b = idx >> 9, u = idx & 511;
            g_AdH[0][b * KK + u] = __float2half_rn(g_x0[idx]);
            g_AdH[0][b * KK + UU + u] = g_AhH[0][idx];
        }
    }
    unsigned gen = TT;
    gsync(++gen);

    const float w  = *ptr_w;
    const float pb = *ptr_b;
    const int arow = warp >> 2;               // attention row within CTA (0/1)
    const int wr = warp & 3;                  // warp-within-row
    const int batt = blockIdx.x * 2 + arow;

    for (int s = 0; s < TT; s++) {
        const __half* Acta = g_AdH[s & 1] + (size_t)rowBase * KK;
        __half* Anext = g_AdH[(s + 1) & 1];

        float d[2][2][4];
        #pragma unroll
        for (int i = 0; i < 2; i++)
            #pragma unroll
            for (int j = 0; j < 2; j++)
                #pragma unroll
                for (int q = 0; q < 4; q++) d[i][j][q] = 0.f;

        gemm_f16_loop<KK>(Acta, WS, SA, d);

        // epilogue: z = d + bias, gates, h -> g_h + Anext
        #pragma unroll
        for (int ms = 0; ms < 2; ms++) {
            #pragma unroll
            for (int ns = 0; ns < 2; ns++) {
                int c0 = colBase + nB + ns * 8 + 2 * tq;
                float bv0 = g_Bdec[c0], bv1 = g_Bdec[c0 + 1];
                float z0 = d[ms][ns][0] + bv0;
                float z1 = d[ms][ns][1] + bv1;
                float z2 = d[ms][ns][2] + bv0;
                float z3 = d[ms][ns][3] + bv1;
                float p0 = __shfl_xor_sync(0xffffffffu, z0, 1);
                float p1 = __shfl_xor_sync(0xffffffffu, z1, 1);
                float p2 = __shfl_xor_sync(0xffffffffu, z2, 1);
                float p3 = __shfl_xor_sync(0xffffffffu, z3, 1);
                if (!(tq & 1)) {
                    int u = c0 >> 2;
                    int r0 = rowBase + mB + ms * 16 + gq;
                    #pragma unroll
                    for (int rr = 0; rr < 2; rr++) {
                        int b = r0 + rr * 8;
                        float zi = rr ? z2 : z0, zf = rr ? z3 : z1;
                        float zg = rr ? p2 : p0, zo = rr ? p3 : p1;
                        int idx = b * UU + u;
                        float c = sigf(zf) * g_c[idx] + sigf(zi) * tanhx(zg);
                        float h = sigf(zo) * tanhx(c);
                        g_c[idx] = c;
                        g_h[idx] = h;
                        Anext[b * KK + UU + u] = __float2half_rn(h);
                    }
                }
            }
        }
        gsync(++gen);

        // ---- attention: 4 warps per batch row, 4-way t batching, online softmax ----
        {
            float hx[16];
            {
                const float4* hb = (const float4*)&g_h[batt * UU];
                float4 q0 = hb[2 * lane], q1 = hb[2 * lane + 1];
                float4 q2 = hb[2 * lane + 64], q3 = hb[2 * lane + 65];
                hx[0]=q0.x; hx[1]=q0.y; hx[2]=q0.z; hx[3]=q0.w;
                hx[4]=q1.x; hx[5]=q1.y; hx[6]=q1.z; hx[7]=q1.w;
                hx[8]=q2.x; hx[9]=q2.y; hx[10]=q2.z; hx[11]=q2.w;
                hx[12]=q3.x; hx[13]=q3.y; hx[14]=q3.z; hx[15]=q3.w;
            }
            float ca[16];
            #pragma unroll
            for (int q = 0; q < 16; q++) ca[q] = 0.f;
            float m = -3.0e38f, Zw = 0.f;

            #pragma unroll 1
            for (int it = 0; it < 16; it++) {
                const int t0 = (it << 4) + (wr << 2);
                uint4 E[4][2];
                #pragma unroll
                for (int j = 0; j < 4; j++) {
                    const uint4* ep = (const uint4*)&g_encH[((size_t)batt * TT + t0 + j) * UU];
                    E[j][0] = ep[lane];
                    E[j][1] = ep[lane + 32];
                }
                float sd[4];
                #pragma unroll
                for (int j = 0; j < 4; j++) {
                    float ex[16];
                    cvt16(E[j], ex);
                    float acc = 0.f;
                    #pragma unroll
                    for (int q = 0; q < 16; q++) acc = fmaf(ex[q], hx[q], acc);
                    sd[j] = acc;
                }
                #pragma unroll
                for (int o = 16; o; o >>= 1) {
                    sd[0] += __shfl_xor_sync(0xffffffffu, sd[0], o);
                    sd[1] += __shfl_xor_sync(0xffffffffu, sd[1], o);
                    sd[2] += __shfl_xor_sync(0xffffffffu, sd[2], o);
                    sd[3] += __shfl_xor_sync(0xffffffffu, sd[3], o);
                }
                #pragma unroll
                for (int j = 0; j < 4; j++) {
                    float sv = sd[j] * w + pb;
                    if (lane == 0) sc[arow * TT + t0 + j] = sv;
                    float mn = fmaxf(m, sv);
                    float scale = __expf(m - mn);
                    float es2 = __expf(sv - mn);
                    Zw = Zw * scale + es2;
                    float ex[16];
                    cvt16(E[j], ex);
                    #pragma unroll
                    for (int q = 0; q < 16; q++) ca[q] = ca[q] * scale + es2 * ex[q];
                    m = mn;
                }
            }
            if (lane == 0) { wm[warp] = m; wz[warp] = Zw; }
            {
                float4* wc = (float4*)&wctx[warp * UU];
                wc[2 * lane]      = make_float4(ca[0], ca[1], ca[2], ca[3]);
                wc[2 * lane + 1]  = make_float4(ca[4], ca[5], ca[6], ca[7]);
                wc[2 * lane + 64] = make_float4(ca[8], ca[9], ca[10], ca[11]);
                wc[2 * lane + 65] = make_float4(ca[12], ca[13], ca[14], ca[15]);
            }
            __syncthreads();

            // combine 4 warps per row; every thread handles u=tid, tid+256 for both rows
            #pragma unroll
            for (int r = 0; r < 2; r++) {
                int bb = blockIdx.x * 2 + r;
                float M = wm[4 * r];
                #pragma unroll
                for (int q = 1; q < 4; q++) M = fmaxf(M, wm[4 * r + q]);
                float Zt = 0.f, x0a = 0.f, x1a = 0.f;
                #pragma unroll
                for (int q = 0; q < 4; q++) {
                    int qq = 4 * r + q;
                    float e = __expf(wm[qq] - M);
                    Zt += e * wz[qq];
                    x0a += e * wctx[qq * UU + tid];
                    x1a += e * wctx[qq * UU + 256 + tid];
                }
                float invZ = 1.0f / Zt;
                Anext[bb * KK + tid]       = __float2half_rn(x0a * invZ);
                Anext[bb * KK + 256 + tid] = __float2half_rn(x1a * invZ);
                out[(size_t)bb * (TT * TT) + (size_t)s * TT + tid] =
                    __expf(sc[r * TT + tid] - M) * invZ;
            }
        }
        gsync(++gen);
    }
}

// ---------------- launch ----------------
extern "C" void kernel_launch(void* const* d_in, const int* in_sizes, int n_in,
                              void* d_out, int out_size) {
    const float* inputs = (const float*)d_in[0];
    const float* score  = (const float*)d_in[1];
    const float* enc_Wx = (const float*)d_in[2];
    const float* enc_Wh = (const float*)d_in[3];
    const float* enc_b  = (const float*)d_in[4];
    const float* dec_Wx = (const float*)d_in[5];
    const float* dec_Wh = (const float*)d_in[6];
    const float* dec_b  = (const float*)d_in[7];
    const float* ptr_w  = (const float*)d_in[8];
    const float* ptr_b  = (const float*)d_in[9];
    float* out = (float*)d_out;

    cudaFuncSetAttribute(encoder_kernel, cudaFuncAttributeMaxDynamicSharedMemorySize, ENC_SMEM);
    cudaFuncSetAttribute(decoder_kernel, cudaFuncAttributeMaxDynamicSharedMemorySize, DEC_SMEM);

    prep_w_enc<<<(UU * ZZ + THR - 1) / THR, THR>>>(enc_Wx, enc_Wh);
    prep_w_dec<<<(KK * ZZ + THR - 1) / THR, THR>>>(dec_Wx, dec_Wh);
    prep_bias_kernel<<<(ZZ + THR - 1) / THR, THR>>>(dec_b);
    prep_x_kernel<<<(int)(((size_t)TT * BB * UU + THR - 1) / THR), THR>>>(inputs, score);
    mean_kernel<<<(BB * UU + THR - 1) / THR, THR>>>();
    init_kernel<<<(BB * UU + THR - 1) / THR, THR>>>();

    dim3 zgrid(ZZ / 64, (TT * BB) / 128);
    zx_kernel<<<zgrid, 256>>>(enc_b);

    encoder_kernel<<<GRID, THR, ENC_SMEM>>>();
    decoder_kernel<<<GRID, THR, DEC_SMEM>>>(ptr_w, ptr_b, out);
}

// round 6
// speedup vs baseline: 4.4255x; 1.0520x over previous
#include <cuda_runtime.h>
#include <cuda_fp16.h>
#include <math.h>

#define BB 256       // batch
#define TT 256       // timesteps
#define FF 511       // raw feature dim
#define UU 512       // units
#define ZZ 2048      // 4*U (gate-interleaved cols: n' = 4u + gate)
#define KK 1024      // decoder fused K
#define GRID 128
#define THR 256
#define AST 40       // A smem stage stride (halfs)

// ---------------- device scratch ----------------
__device__ float  g_Xt[(size_t)TT * BB * UU];    // [t][b][u] tf32 input (score appended)
__device__ float  g_Zx[(size_t)TT * BB * ZZ];    // x@Wx + bias (gate-interleaved), fp32
__device__ __half g_encH[(size_t)BB * TT * UU];  // [b][t][u] encoder hidden, fp16
__device__ float  g_Wxe[(size_t)UU * ZZ];        // enc Wx interleaved, tf32 (for zx GEMM)
__device__ __half g_WheT[(size_t)ZZ * UU];       // enc Wh, [n'][k] n-major, fp16
__device__ __half g_WdT[(size_t)ZZ * KK];        // dec [Wx;Wh], [n'][k] n-major, fp16
__device__ float  g_Bdec[ZZ];
__device__ __half g_AhH[2][BB * UU];             // encoder h operand, fp16
__device__ __half g_AdH[2][BB * KK];             // decoder [xin|h] operand, fp16
__device__ float  g_h[BB * UU];                  // fp32 h for attention
__device__ float  g_c[BB * UU];
__device__ float  g_x0[BB * UU];
__device__ unsigned g_cnt, g_gen;

// ---------------- helpers ----------------
__device__ __forceinline__ float tf32r(float x) {
    unsigned r; asm("cvt.rna.tf32.f32 %0, %1;" : "=r"(r) : "f"(x));
    return __uint_as_float(r);
}
__device__ __forceinline__ float sigf(float x) { return 1.0f / (1.0f + __expf(-x)); }
__device__ __forceinline__ float tanhx(float x) { return 2.0f / (1.0f + __expf(-2.0f * x)) - 1.0f; }
__device__ __forceinline__ void h2f(unsigned v, float& a, float& b) {
    float2 f = __half22float2(*reinterpret_cast<const __half2*>(&v));
    a = f.x; b = f.y;
}
__device__ __forceinline__ void cvt16(const uint4 E[2], float ex[16]) {
    h2f(E[0].x, ex[0], ex[1]);   h2f(E[0].y, ex[2], ex[3]);
    h2f(E[0].z, ex[4], ex[5]);   h2f(E[0].w, ex[6], ex[7]);
    h2f(E[1].x, ex[8], ex[9]);   h2f(E[1].y, ex[10], ex[11]);
    h2f(E[1].z, ex[12], ex[13]); h2f(E[1].w, ex[14], ex[15]);
}

// grid barrier, cooperative-groups style: release-atomic arrive, acquire poll
__device__ __forceinline__ void gsync(unsigned target) {
    __syncthreads();
    if (threadIdx.x == 0) {
        unsigned old;
        asm volatile("atom.add.release.gpu.u32 %0, [%1], 1;"
                     : "=r"(old) : "l"(&g_cnt) : "memory");
        if (old == GRID - 1u) {
            g_cnt = 0u;
            asm volatile("st.release.gpu.u32 [%0], %1;" :: "l"(&g_gen), "r"(target) : "memory");
        } else {
            unsigned v;
            do {
                __nanosleep(20);
                asm volatile("ld.acquire.gpu.u32 %0, [%1];" : "=r"(v) : "l"(&g_gen) : "memory");
            } while (v < target);
        }
    }
    __syncthreads();
}

__device__ __forceinline__ void mma_tf32(float d[4], const unsigned a[4], const unsigned b[2]) {
    asm volatile("mma.sync.aligned.m16n8k8.row.col.f32.tf32.tf32.f32 "
                 "{%0,%1,%2,%3}, {%4,%5,%6,%7}, {%8,%9}, {%0,%1,%2,%3};\n"
                 : "+f"(d[0]), "+f"(d[1]), "+f"(d[2]), "+f"(d[3])
                 : "r"(a[0]), "r"(a[1]), "r"(a[2]), "r"(a[3]), "r"(b[0]), "r"(b[1]));
}
__device__ __forceinline__ void mma_f16(float d[4], const unsigned a[4], const unsigned b[2]) {
    asm volatile("mma.sync.aligned.m16n8k16.row.col.f32.f16.f16.f32 "
                 "{%0,%1,%2,%3}, {%4,%5,%6,%7}, {%8,%9}, {%0,%1,%2,%3};\n"
                 : "+f"(d[0]), "+f"(d[1]), "+f"(d[2]), "+f"(d[3])
                 : "r"(a[0]), "r"(a[1]), "r"(a[2]), "r"(a[3]), "r"(b[0]), "r"(b[1]));
}
__device__ __forceinline__ void ldsm_x4(unsigned& r0, unsigned& r1, unsigned& r2, unsigned& r3,
                                        unsigned addr) {
    asm volatile("ldmatrix.sync.aligned.m8n8.x4.shared.b16 {%0,%1,%2,%3}, [%4];"
                 : "=r"(r0), "=r"(r1), "=r"(r2), "=r"(r3) : "r"(addr));
}

// ---------------- prep: ALL one-time setup in two kernels ----------------
__global__ void prepA_kernel(const float* __restrict__ inputs, const float* __restrict__ score,
                             const float* __restrict__ eWx, const float* __restrict__ eWh,
                             const float* __restrict__ dWx, const float* __restrict__ dWh,
                             const float* __restrict__ db) {
    size_t idx = (size_t)blockIdx.x * blockDim.x + threadIdx.x;
    if (idx < (size_t)KK * ZZ) {                       // decoder W transpose+interleave
        int k = (int)(idx / ZZ), np = (int)(idx % ZZ);
        int n = (np & 3) * UU + (np >> 2);
        float v = (k < UU) ? dWx[(size_t)k * ZZ + n] : dWh[(size_t)(k - UU) * ZZ + n];
        g_WdT[(size_t)np * KK + k] = __float2half_rn(v);
    }
    if (idx < (size_t)UU * ZZ) {                       // encoder W
        int k = (int)(idx / ZZ), np = (int)(idx % ZZ);
        int n = (np & 3) * UU + (np >> 2);
        g_Wxe[idx] = tf32r(eWx[(size_t)k * ZZ + n]);
        g_WheT[(size_t)np * UU + k] = __float2half_rn(eWh[(size_t)k * ZZ + n]);
    }
    if (idx < ZZ) g_Bdec[idx] = db[((int)idx & 3) * UU + ((int)idx >> 2)];
    if (idx < BB * UU) {                               // init + dec_in0 (mean over t)
        int i = (int)idx;
        g_AhH[0][i] = __float2half_rn(0.f);
        g_c[i] = 0.f;
        int b = i >> 9, u = i & 511;
        float s;
        if (u < FF) {
            const float* ip = inputs + (size_t)b * TT * FF + u;
            float acc = 0.f;
            #pragma unroll 4
            for (int t = 0; t < TT; t++) acc += ip[(size_t)t * FF];
            s = acc * (1.0f / TT);
        } else {
            s = score[b];
        }
        g_x0[i] = s;
    }
    if (idx == 0) { g_cnt = 0u; g_gen = 0u; }
}

__global__ void prepX_kernel(const float* __restrict__ inputs, const float* __restrict__ score) {
    size_t idx = (size_t)blockIdx.x * blockDim.x + threadIdx.x;
    if (idx >= (size_t)TT * BB * UU) return;
    int t = (int)(idx / (BB * UU));
    int rem = (int)(idx % (BB * UU));
    int b = rem / UU, u = rem % UU;
    float v = (u < FF) ? inputs[((size_t)b * TT + t) * FF + u] : score[b];
    g_Xt[idx] = tf32r(v);
}

// ---------------- Zx = X @ Wxe + bias : big parallel tf32 GEMM ----------------
__global__ void __launch_bounds__(256) zx_kernel(const float* __restrict__ be) {
    __shared__ float SAx[2][128 * 20];
    __shared__ float SBx[2][16 * 72];
    const int tid = threadIdx.x, lane = tid & 31, wid = tid >> 5;
    const int rowBase = blockIdx.y << 7;
    const int colBase = blockIdx.x << 6;
    const int mB = (wid >> 1) << 5;
    const int nB = (wid & 1) << 5;
    const int gq = lane >> 2, tq = lane & 3;

    const int ar = tid >> 2;
    const int akq = (tid & 3) << 2;
    const int bkr = tid >> 4, bnq = (tid & 15) << 2;
    const float* aptrA = g_Xt + (size_t)(rowBase + ar) * UU + akq;
    const float* aptrB = aptrA + (size_t)64 * UU;
    const float* bptr = g_Wxe + (size_t)bkr * ZZ + colBase + bnq;

    float4 rAa0 = *(const float4*)(aptrA);
    float4 rAb0 = *(const float4*)(aptrB);
    float4 rB0  = *(const float4*)(bptr);
    float4 rAa1 = *(const float4*)(aptrA + 16);
    float4 rAb1 = *(const float4*)(aptrB + 16);
    float4 rB1  = *(const float4*)(bptr + (size_t)16 * ZZ);
    *(float4*)&SAx[0][ar * 20 + akq] = rAa0;
    *(float4*)&SAx[0][(64 + ar) * 20 + akq] = rAb0;
    *(float4*)&SBx[0][bkr * 72 + bnq] = rB0;
    __syncthreads();

    float d[2][4][4];
    #pragma unroll
    for (int i = 0; i < 2; i++)
        #pragma unroll
        for (int j = 0; j < 4; j++)
            #pragma unroll
            for (int q = 0; q < 4; q++) d[i][j][q] = 0.f;

    #pragma unroll 1
    for (int kt = 0; kt < 32; kt += 2) {
        if (kt + 2 < 32) {
            rAa0 = *(const float4*)(aptrA + (kt + 2) * 16);
            rAb0 = *(const float4*)(aptrB + (kt + 2) * 16);
            rB0  = *(const float4*)(bptr + (size_t)(kt + 2) * 16 * ZZ);
        }
        #pragma unroll
        for (int kc = 0; kc < 16; kc += 8) {
            unsigned a0[4], a1[4], bbf[4][2];
            const float* A0 = SAx[0] + (mB + gq) * 20 + kc + tq;
            a0[0] = __float_as_uint(A0[0]);      a0[1] = __float_as_uint(A0[8 * 20]);
            a0[2] = __float_as_uint(A0[4]);      a0[3] = __float_as_uint(A0[8 * 20 + 4]);
            const float* A1 = A0 + 16 * 20;
            a1[0] = __float_as_uint(A1[0]);      a1[1] = __float_as_uint(A1[8 * 20]);
            a1[2] = __float_as_uint(A1[4]);      a1[3] = __float_as_uint(A1[8 * 20 + 4]);
            const float* B0 = SBx[0] + (kc + tq) * 72 + nB + gq;
            #pragma unroll
            for (int ns = 0; ns < 4; ns++) {
                bbf[ns][0] = __float_as_uint(B0[ns * 8]);
                bbf[ns][1] = __float_as_uint(B0[4 * 72 + ns * 8]);
            }
            #pragma unroll
            for (int ns = 0; ns < 4; ns++) { mma_tf32(d[0][ns], a0, bbf[ns]); mma_tf32(d[1][ns], a1, bbf[ns]); }
        }
        *(float4*)&SAx[1][ar * 20 + akq] = rAa1;
        *(float4*)&SAx[1][(64 + ar) * 20 + akq] = rAb1;
        *(float4*)&SBx[1][bkr * 72 + bnq] = rB1;
        __syncthreads();

        if (kt + 3 < 32) {
            rAa1 = *(const float4*)(aptrA + (kt + 3) * 16);
            rAb1 = *(const float4*)(aptrB + (kt + 3) * 16);
            rB1  = *(const float4*)(bptr + (size_t)(kt + 3) * 16 * ZZ);
        }
        #pragma unroll
        for (int kc = 0; kc < 16; kc += 8) {
            unsigned a0[4], a1[4], bbf[4][2];
            const float* A0 = SAx[1] + (mB + gq) * 20 + kc + tq;
            a0[0] = __float_as_uint(A0[0]);      a0[1] = __float_as_uint(A0[8 * 20]);
            a0[2] = __float_as_uint(A0[4]);      a0[3] = __float_as_uint(A0[8 * 20 + 4]);
            const float* A1 = A0 + 16 * 20;
            a1[0] = __float_as_uint(A1[0]);      a1[1] = __float_as_uint(A1[8 * 20]);
            a1[2] = __float_as_uint(A1[4]);      a1[3] = __float_as_uint(A1[8 * 20 + 4]);
            const float* B0 = SBx[1] + (kc + tq) * 72 + nB + gq;
            #pragma unroll
            for (int ns = 0; ns < 4; ns++) {
                bbf[ns][0] = __float_as_uint(B0[ns * 8]);
                bbf[ns][1] = __float_as_uint(B0[4 * 72 + ns * 8]);
            }
            #pragma unroll
            for (int ns = 0; ns < 4; ns++) { mma_tf32(d[0][ns], a0, bbf[ns]); mma_tf32(d[1][ns], a1, bbf[ns]); }
        }
        if (kt + 2 < 32) {
            *(float4*)&SAx[0][ar * 20 + akq] = rAa0;
            *(float4*)&SAx[0][(64 + ar) * 20 + akq] = rAb0;
            *(float4*)&SBx[0][bkr * 72 + bnq] = rB0;
        }
        __syncthreads();
    }

    #pragma unroll
    for (int ms = 0; ms < 2; ms++) {
        #pragma unroll
        for (int ns = 0; ns < 4; ns++) {
            int r0 = rowBase + mB + ms * 16 + gq;
            int c0 = colBase + nB + ns * 8 + 2 * tq;
            int g0 = c0 & 3, u = c0 >> 2;
            float b0 = be[g0 * UU + u], b1 = be[(g0 + 1) * UU + u];
            float2 o1 = { d[ms][ns][0] + b0, d[ms][ns][1] + b1 };
            float2 o2 = { d[ms][ns][2] + b0, d[ms][ns][3] + b1 };
            *(float2*)&g_Zx[(size_t)r0 * ZZ + c0] = o1;
            *(float2*)&g_Zx[(size_t)(r0 + 8) * ZZ + c0] = o2;
        }
    }
}

// ---------------- fp16 W-stationary GEMM mainloop (ldmatrix.x4) ----------------
// CTA tile 64x64, 8 warps 2(M)x4(N), warp tile 32x16, mma m16n8k16.
template<int KD>
__device__ __forceinline__ void gemm_f16_loop(const __half* __restrict__ Acta,
                                              const __half* __restrict__ WS,
                                              __half* __restrict__ SA,
                                              float d[2][2][4]) {
    const int tid = threadIdx.x, lane = tid & 31, wid = tid >> 5;
    const int mB = (wid >> 2) << 5;
    const int nB = (wid & 3) << 4;
    const int WSTR = KD + 8;
    // ldmatrix lane address components
    const int aRow = (lane & 7) + ((lane >> 3) & 1) * 8;       // m within 16-tile
    const int aK   = (lane >> 4) << 3;                          // k offset 0/8
    const int bN   = ((lane >> 4) << 3) + (lane & 7);           // n within 16-tile
    const int bK   = ((lane >> 3) & 1) << 3;                    // k offset 0/8

    unsigned saBase = (unsigned)__cvta_generic_to_shared(SA);
    unsigned wsAddr = (unsigned)__cvta_generic_to_shared(WS)
                    + (unsigned)(((nB + bN) * WSTR + bK) * 2);
    unsigned aAddr = saBase + (unsigned)(((mB + aRow) * AST + aK) * 2);

    const int r = tid >> 2, j8 = (tid & 3) << 3;
    const __half* ap = Acta + (size_t)r * KD + j8;

    uint4 p0 = *(const uint4*)(ap);
    uint4 p1 = *(const uint4*)(ap + 32);
    *(uint4*)&SA[r * AST + j8] = p0;
    __syncthreads();

    constexpr int S = KD / 32;
    #pragma unroll 1
    for (int s = 0; s < S; s++) {
        uint4 nxt;
        if (s + 2 < S) nxt = *(const uint4*)(ap + (s + 2) * 32);
        if (s + 1 < S) *(uint4*)&SA[((s + 1) % 3) * (64 * AST) + r * AST + j8] = p1;

        unsigned sa = aAddr + (unsigned)(((s % 3) * (64 * AST)) * 2);
        unsigned wk = wsAddr + (unsigned)((s << 5) * 2);
        #pragma unroll
        for (int kc = 0; kc < 32; kc += 16) {
            unsigned a0[4], a1[4], bb[4];
            ldsm_x4(a0[0], a0[1], a0[2], a0[3], sa + kc * 2);
            ldsm_x4(a1[0], a1[1], a1[2], a1[3], sa + (16 * AST + kc) * 2);
            ldsm_x4(bb[0], bb[1], bb[2], bb[3], wk + kc * 2);
            unsigned b0[2] = { bb[0], bb[1] };
            unsigned b1[2] = { bb[2], bb[3] };
            mma_f16(d[0][0], a0, b0);
            mma_f16(d[0][1], a0, b1);
            mma_f16(d[1][0], a1, b0);
            mma_f16(d[1][1], a1, b1);
        }
        __syncthreads();
        p1 = nxt;
    }
}

// ---------------- persistent encoder ----------------
#define ENC_WS_H (64 * (UU + 8))
#define ENC_SMEM ((ENC_WS_H + 3 * 64 * AST) * 2)

__global__ void __launch_bounds__(THR, 1) encoder_kernel() {
    extern __shared__ __half es[];
    __half* WS = es;
    __half* SA = es + ENC_WS_H;

    const int tid = threadIdx.x, lane = tid & 31, wid = tid >> 5;
    const int rowBase = (blockIdx.x >> 5) << 6;
    const int colBase = (blockIdx.x & 31) << 6;
    const int mB = (wid >> 2) << 5;
    const int nB = (wid & 3) << 4;
    const int gq = lane >> 2, tq = lane & 3;

    for (int j = tid; j < 64 * 64; j += THR) {
        int row = j >> 6, ch = (j & 63) << 3;
        *(uint4*)&WS[row * (UU + 8) + ch] =
            *(const uint4*)&g_WheT[(size_t)(colBase + row) * UU + ch];
    }
    __syncthreads();

    unsigned gen = 0;
    for (int t = 0; t < TT; t++) {
        const __half* Acta = g_AhH[t & 1] + (size_t)rowBase * UU;
        __half* An = g_AhH[(t + 1) & 1];

        float d[2][2][4];
        #pragma unroll
        for (int i = 0; i < 2; i++)
            #pragma unroll
            for (int j = 0; j < 2; j++)
                #pragma unroll
                for (int q = 0; q < 4; q++) d[i][j][q] = 0.f;

        gemm_f16_loop<UU>(Acta, WS, SA, d);

        #pragma unroll
        for (int ms = 0; ms < 2; ms++) {
            #pragma unroll
            for (int ns = 0; ns < 2; ns++) {
                int r0 = rowBase + mB + ms * 16 + gq;
                int c0 = colBase + nB + ns * 8 + 2 * tq;
                const float* zx = &g_Zx[((size_t)t * BB + r0) * ZZ + c0];
                float2 zxa = *(const float2*)zx;
                float2 zxb = *(const float2*)(zx + (size_t)8 * ZZ);
                float z0 = d[ms][ns][0] + zxa.x;
                float z1 = d[ms][ns][1] + zxa.y;
                float z2 = d[ms][ns][2] + zxb.x;
                float z3 = d[ms][ns][3] + zxb.y;
                float p0 = __shfl_xor_sync(0xffffffffu, z0, 1);
                float p1 = __shfl_xor_sync(0xffffffffu, z1, 1);
                float p2 = __shfl_xor_sync(0xffffffffu, z2, 1);
                float p3 = __shfl_xor_sync(0xffffffffu, z3, 1);
                if (!(tq & 1)) {
                    int u = c0 >> 2;
                    #pragma unroll
                    for (int rr = 0; rr < 2; rr++) {
                        int b = r0 + rr * 8;
                        float zi = rr ? z2 : z0, zf = rr ? z3 : z1;
                        float zg = rr ? p2 : p0, zo = rr ? p3 : p1;
                        int idx = b * UU + u;
                        float c = sigf(zf) * g_c[idx] + sigf(zi) * tanhx(zg);
                        float h = sigf(zo) * tanhx(c);
                        g_c[idx] = c;
                        __half hh = __float2half_rn(h);
                        An[idx] = hh;
                        g_encH[((size_t)b * TT + t) * UU + u] = hh;
                    }
                }
            }
        }
        gsync(++gen);
    }
}

// ---------------- decoder prologue (separate launch -> decoder is 6th kernel) ----------------
__global__ void decprep_kernel() {
    int idx = blockIdx.x * THR + threadIdx.x;
    if (idx >= BB * UU) return;
    int b = idx >> 9, u = idx & 511;
    g_AdH[0][b * KK + u] = __float2half_rn(g_x0[idx]);
    g_AdH[0][b * KK + UU + u] = g_AhH[0][idx];   // encoder final h (t=255 wrote buf 0)
}

// ---------------- persistent decoder ----------------
#define DEC_WS_H (64 * (KK + 8))
#define DEC_SA_H (3 * 64 * AST)
#define DEC_SMEM (DEC_WS_H * 2 + DEC_SA_H * 2 + (8 * UU + 2 * TT + 16) * 4)

__global__ void __launch_bounds__(THR, 1) decoder_kernel(
    const float* __restrict__ ptr_w, const float* __restrict__ ptr_b,
    float* __restrict__ out) {
    extern __shared__ __half ds[];
    __half* WS = ds;
    __half* SA = ds + DEC_WS_H;
    float* wctx = (float*)(ds + DEC_WS_H + DEC_SA_H);   // [8][512]
    float* sc   = wctx + 8 * UU;                        // [2][256]
    float* wm   = sc + 2 * TT;                          // [8]
    float* wz   = wm + 8;                               // [8]

    const int tid = threadIdx.x, lane = tid & 31, warp = tid >> 5;
    const int rowBase = (blockIdx.x >> 5) << 6;
    const int colBase = (blockIdx.x & 31) << 6;
    const int mB = (warp >> 2) << 5;
    const int nB = (warp & 3) << 4;
    const int gq = lane >> 2, tq = lane & 3;

    for (int j = tid; j < 64 * 128; j += THR) {
        int row = j >> 7, ch = (j & 127) << 3;
        *(uint4*)&WS[row * (KK + 8) + ch] =
            *(const uint4*)&g_WdT[(size_t)(colBase + row) * KK + ch];
    }
    __syncthreads();

    const float w  = *ptr_w;
    const float pb = *ptr_b;
    const int arow = warp >> 2;               // attention row within CTA (0/1)
    const int wr = warp & 3;                  // warp-within-row
    const int batt = blockIdx.x * 2 + arow;

    unsigned gen = TT;
    for (int s = 0; s < TT; s++) {
        const __half* Acta = g_AdH[s & 1] + (size_t)rowBase * KK;
        __half* Anext = g_AdH[(s + 1) & 1];

        float d[2][2][4];
        #pragma unroll
        for (int i = 0; i < 2; i++)
            #pragma unroll
            for (int j = 0; j < 2; j++)
                #pragma unroll
                for (int q = 0; q < 4; q++) d[i][j][q] = 0.f;

        gemm_f16_loop<KK>(Acta, WS, SA, d);

        #pragma unroll
        for (int ms = 0; ms < 2; ms++) {
            #pragma unroll
            for (int ns = 0; ns < 2; ns++) {
                int c0 = colBase + nB + ns * 8 + 2 * tq;
                float bv0 = g_Bdec[c0], bv1 = g_Bdec[c0 + 1];
                float z0 = d[ms][ns][0] + bv0;
                float z1 = d[ms][ns][1] + bv1;
                float z2 = d[ms][ns][2] + bv0;
                float z3 = d[ms][ns][3] + bv1;
                float p0 = __shfl_xor_sync(0xffffffffu, z0, 1);
                float p1 = __shfl_xor_sync(0xffffffffu, z1, 1);
                float p2 = __shfl_xor_sync(0xffffffffu, z2, 1);
                float p3 = __shfl_xor_sync(0xffffffffu, z3, 1);
                if (!(tq & 1)) {
                    int u = c0 >> 2;
                    int r0 = rowBase + mB + ms * 16 + gq;
                    #pragma unroll
                    for (int rr = 0; rr < 2; rr++) {
                        int b = r0 + rr * 8;
                        float zi = rr ? z2 : z0, zf = rr ? z3 : z1;
                        float zg = rr ? p2 : p0, zo = rr ? p3 : p1;
                        int idx = b * UU + u;
                        float c = sigf(zf) * g_c[idx] + sigf(zi) * tanhx(zg);
                        float h = sigf(zo) * tanhx(c);
                        g_c[idx] = c;
                        g_h[idx] = h;
                        Anext[b * KK + UU + u] = __float2half_rn(h);
                    }
                }
            }
        }
        gsync(++gen);

        // ---- attention: 4 warps/row, 4-way t batching, block-local online softmax ----
        {
            float hx[16];
            {
                const float4* hb = (const float4*)&g_h[batt * UU];
                float4 q0 = hb[2 * lane], q1 = hb[2 * lane + 1];
                float4 q2 = hb[2 * lane + 64], q3 = hb[2 * lane + 65];
                hx[0]=q0.x; hx[1]=q0.y; hx[2]=q0.z; hx[3]=q0.w;
                hx[4]=q1.x; hx[5]=q1.y; hx[6]=q1.z; hx[7]=q1.w;
                hx[8]=q2.x; hx[9]=q2.y; hx[10]=q2.z; hx[11]=q2.w;
                hx[12]=q3.x; hx[13]=q3.y; hx[14]=q3.z; hx[15]=q3.w;
            }
            float ca[16];
            #pragma unroll
            for (int q = 0; q < 16; q++) ca[q] = 0.f;
            float m = -3.0e38f, Zw = 0.f;

            #pragma unroll 1
            for (int it = 0; it < 16; it++) {
                const int t0 = (it << 4) + (wr << 2);
                uint4 E[4][2];
                #pragma unroll
                for (int j = 0; j < 4; j++) {
                    const uint4* ep = (const uint4*)&g_encH[((size_t)batt * TT + t0 + j) * UU];
                    E[j][0] = ep[lane];
                    E[j][1] = ep[lane + 32];
                }
                float sv[4];
                #pragma unroll
                for (int j = 0; j < 4; j++) {
                    float ex[16];
                    cvt16(E[j], ex);
                    float acc = 0.f;
                    #pragma unroll
                    for (int q = 0; q < 16; q++) acc = fmaf(ex[q], hx[q], acc);
                    sv[j] = acc;
                }
                #pragma unroll
                for (int o = 16; o; o >>= 1) {
                    sv[0] += __shfl_xor_sync(0xffffffffu, sv[0], o);
                    sv[1] += __shfl_xor_sync(0xffffffffu, sv[1], o);
                    sv[2] += __shfl_xor_sync(0xffffffffu, sv[2], o);
                    sv[3] += __shfl_xor_sync(0xffffffffu, sv[3], o);
                }
                #pragma unroll
                for (int j = 0; j < 4; j++) sv[j] = sv[j] * w + pb;
                if (lane == 0) {
                    sc[arow * TT + t0 + 0] = sv[0];
                    sc[arow * TT + t0 + 1] = sv[1];
                    sc[arow * TT + t0 + 2] = sv[2];
                    sc[arow * TT + t0 + 3] = sv[3];
                }
                float mloc = fmaxf(fmaxf(sv[0], sv[1]), fmaxf(sv[2], sv[3]));
                float mn = fmaxf(m, mloc);
                float scale = __expf(m - mn);
                float e0 = __expf(sv[0] - mn);
                float e1 = __expf(sv[1] - mn);
                float e2 = __expf(sv[2] - mn);
                float e3 = __expf(sv[3] - mn);
                Zw = Zw * scale + ((e0 + e1) + (e2 + e3));
                float ex[16];
                cvt16(E[0], ex);
                #pragma unroll
                for (int q = 0; q < 16; q++) ca[q] = ca[q] * scale + e0 * ex[q];
                cvt16(E[1], ex);
                #pragma unroll
                for (int q = 0; q < 16; q++) ca[q] = fmaf(e1, ex[q], ca[q]);
                cvt16(E[2], ex);
                #pragma unroll
                for (int q = 0; q < 16; q++) ca[q] = fmaf(e2, ex[q], ca[q]);
                cvt16(E[3], ex);
                #pragma unroll
                for (int q = 0; q < 16; q++) ca[q] = fmaf(e3, ex[q], ca[q]);
                m = mn;
            }
            if (lane == 0) { wm[warp] = m; wz[warp] = Zw; }
            {
                float4* wc = (float4*)&wctx[warp * UU];
                wc[2 * lane]      = make_float4(ca[0], ca[1], ca[2], ca[3]);
                wc[2 * lane + 1]  = make_float4(ca[4], ca[5], ca[6], ca[7]);
                wc[2 * lane + 64] = make_float4(ca[8], ca[9], ca[10], ca[11]);
                wc[2 * lane + 65] = make_float4(ca[12], ca[13], ca[14], ca[15]);
            }
            __syncthreads();

            #pragma unroll
            for (int r = 0; r < 2; r++) {
                int bb = blockIdx.x * 2 + r;
                float M = wm[4 * r];
                #pragma unroll
                for (int q = 1; q < 4; q++) M = fmaxf(M, wm[4 * r + q]);
                float Zt = 0.f, x0a = 0.f, x1a = 0.f;
                #pragma unroll
                for (int q = 0; q < 4; q++) {
                    int qq = 4 * r + q;
                    float e = __expf(wm[qq] - M);
                    Zt += e * wz[qq];
                    x0a += e * wctx[qq * UU + tid];
                    x1a += e * wctx[qq * UU + 256 + tid];
                }
                float invZ = 1.0f / Zt;
                Anext[bb * KK + tid]       = __float2half_rn(x0a * invZ);
                Anext[bb * KK + 256 + tid] = __float2half_rn(x1a * invZ);
                out[(size_t)bb * (TT * TT) + (size_t)s * TT + tid] =
                    __expf(sc[r * TT + tid] - M) * invZ;
            }
        }
        gsync(++gen);
    }
}

// ---------------- launch: exactly 6 kernels (decoder lands on ncu -s 5) ----------------
extern "C" void kernel_launch(void* const* d_in, const int* in_sizes, int n_in,
                              void* d_out, int out_size) {
    const float* inputs = (const float*)d_in[0];
    const float* score  = (const float*)d_in[1];
    const float* enc_Wx = (const float*)d_in[2];
    const float* enc_Wh = (const float*)d_in[3];
    const float* enc_b  = (const float*)d_in[4];
    const float* dec_Wx = (const float*)d_in[5];
    const float* dec_Wh = (const float*)d_in[6];
    const float* dec_b  = (const float*)d_in[7];
    const float* ptr_w  = (const float*)d_in[8];
    const float* ptr_b  = (const float*)d_in[9];
    float* out = (float*)d_out;

    cudaFuncSetAttribute(encoder_kernel, cudaFuncAttributeMaxDynamicSharedMemorySize, ENC_SMEM);
    cudaFuncSetAttribute(decoder_kernel, cudaFuncAttributeMaxDynamicSharedMemorySize, DEC_SMEM);

    prepA_kernel<<<(int)(((size_t)KK * ZZ + THR - 1) / THR), THR>>>(
        inputs, score, enc_Wx, enc_Wh, dec_Wx, dec_Wh, dec_b);
    prepX_kernel<<<(int)(((size_t)TT * BB * UU + THR - 1) / THR), THR>>>(inputs, score);

    dim3 zgrid(ZZ / 64, (TT * BB) / 128);
    zx_kernel<<<zgrid, 256>>>(enc_b);

    encoder_kernel<<<GRID, THR, ENC_SMEM>>>();
    decprep_kernel<<<(BB * UU + THR - 1) / THR, THR>>>();
    decoder_kernel<<<GRID, THR, DEC_SMEM>>>(ptr_w, ptr_b, out);
}

// round 7
// speedup vs baseline: 5.0188x; 1.1341x over previous
#include <cuda_runtime.h>
#include <cuda_fp16.h>
#include <math.h>

#define BB 256       // batch
#define TT 256       // timesteps
#define FF 511       // raw feature dim
#define UU 512       // units
#define ZZ 2048      // 4*U (gate-interleaved cols: n' = 4u + gate)
#define KK 1024      // decoder fused K
#define GRID 128
#define THR 256      // prep/zx block
#define THRP 512     // persistent kernels: 16 warps
#define AST 40       // A smem stage stride (halfs)

// ---------------- device scratch ----------------
__device__ float  g_Xt[(size_t)TT * BB * UU];    // [t][b][u] tf32 input (score appended)
__device__ float  g_Zx[(size_t)TT * BB * ZZ];    // x@Wx + bias (gate-interleaved), fp32
__device__ __half g_encH[(size_t)BB * TT * UU];  // [b][t][u] encoder hidden, fp16
__device__ float  g_Wxe[(size_t)UU * ZZ];        // enc Wx interleaved, tf32 (for zx GEMM)
__device__ __half g_WheT[(size_t)ZZ * UU];       // enc Wh, [n'][k] n-major, fp16
__device__ __half g_WdT[(size_t)ZZ * KK];        // dec [Wx;Wh], [n'][k] n-major, fp16
__device__ float  g_Bdec[ZZ];
__device__ __half g_AhH[2][BB * UU];             // encoder h operand, fp16
__device__ __half g_AdH[2][BB * KK];             // decoder [xin|h] operand, fp16
__device__ float  g_h[BB * UU];                  // fp32 h for attention
__device__ float  g_c[BB * UU];
__device__ float  g_x0[BB * UU];
__device__ unsigned g_cnt, g_gen;

// ---------------- helpers ----------------
__device__ __forceinline__ float tf32r(float x) {
    unsigned r; asm("cvt.rna.tf32.f32 %0, %1;" : "=r"(r) : "f"(x));
    return __uint_as_float(r);
}
__device__ __forceinline__ float sigf(float x) { return 1.0f / (1.0f + __expf(-x)); }
__device__ __forceinline__ float tanhx(float x) { return 2.0f / (1.0f + __expf(-2.0f * x)) - 1.0f; }
__device__ __forceinline__ void h2f(unsigned v, float& a, float& b) {
    float2 f = __half22float2(*reinterpret_cast<const __half2*>(&v));
    a = f.x; b = f.y;
}
__device__ __forceinline__ void cvt16(const uint4 E[2], float ex[16]) {
    h2f(E[0].x, ex[0], ex[1]);   h2f(E[0].y, ex[2], ex[3]);
    h2f(E[0].z, ex[4], ex[5]);   h2f(E[0].w, ex[6], ex[7]);
    h2f(E[1].x, ex[8], ex[9]);   h2f(E[1].y, ex[10], ex[11]);
    h2f(E[1].z, ex[12], ex[13]); h2f(E[1].w, ex[14], ex[15]);
}

// grid barrier: release-atomic arrive, acquire poll
__device__ __forceinline__ void gsync(unsigned target) {
    __syncthreads();
    if (threadIdx.x == 0) {
        unsigned old;
        asm volatile("atom.add.release.gpu.u32 %0, [%1], 1;"
                     : "=r"(old) : "l"(&g_cnt) : "memory");
        if (old == GRID - 1u) {
            g_cnt = 0u;
            asm volatile("st.release.gpu.u32 [%0], %1;" :: "l"(&g_gen), "r"(target) : "memory");
        } else {
            unsigned v;
            do {
                __nanosleep(20);
                asm volatile("ld.acquire.gpu.u32 %0, [%1];" : "=r"(v) : "l"(&g_gen) : "memory");
            } while (v < target);
        }
    }
    __syncthreads();
}

__device__ __forceinline__ void mma_tf32(float d[4], const unsigned a[4], const unsigned b[2]) {
    asm volatile("mma.sync.aligned.m16n8k8.row.col.f32.tf32.tf32.f32 "
                 "{%0,%1,%2,%3}, {%4,%5,%6,%7}, {%8,%9}, {%0,%1,%2,%3};\n"
                 : "+f"(d[0]), "+f"(d[1]), "+f"(d[2]), "+f"(d[3])
                 : "r"(a[0]), "r"(a[1]), "r"(a[2]), "r"(a[3]), "r"(b[0]), "r"(b[1]));
}
__device__ __forceinline__ void mma_f16(float d[4], const unsigned a[4], const unsigned b[2]) {
    asm volatile("mma.sync.aligned.m16n8k16.row.col.f32.f16.f16.f32 "
                 "{%0,%1,%2,%3}, {%4,%5,%6,%7}, {%8,%9}, {%0,%1,%2,%3};\n"
                 : "+f"(d[0]), "+f"(d[1]), "+f"(d[2]), "+f"(d[3])
                 : "r"(a[0]), "r"(a[1]), "r"(a[2]), "r"(a[3]), "r"(b[0]), "r"(b[1]));
}
__device__ __forceinline__ void ldsm_x4(unsigned& r0, unsigned& r1, unsigned& r2, unsigned& r3,
                                        unsigned addr) {
    asm volatile("ldmatrix.sync.aligned.m8n8.x4.shared.b16 {%0,%1,%2,%3}, [%4];"
                 : "=r"(r0), "=r"(r1), "=r"(r2), "=r"(r3) : "r"(addr));
}

// ---------------- prep ----------------
__global__ void prepA_kernel(const float* __restrict__ inputs, const float* __restrict__ score,
                             const float* __restrict__ eWx, const float* __restrict__ eWh,
                             const float* __restrict__ dWx, const float* __restrict__ dWh,
                             const float* __restrict__ db) {
    size_t idx = (size_t)blockIdx.x * blockDim.x + threadIdx.x;
    if (idx < (size_t)KK * ZZ) {
        int k = (int)(idx / ZZ), np = (int)(idx % ZZ);
        int n = (np & 3) * UU + (np >> 2);
        float v = (k < UU) ? dWx[(size_t)k * ZZ + n] : dWh[(size_t)(k - UU) * ZZ + n];
        g_WdT[(size_t)np * KK + k] = __float2half_rn(v);
    }
    if (idx < (size_t)UU * ZZ) {
        int k = (int)(idx / ZZ), np = (int)(idx % ZZ);
        int n = (np & 3) * UU + (np >> 2);
        g_Wxe[idx] = tf32r(eWx[(size_t)k * ZZ + n]);
        g_WheT[(size_t)np * UU + k] = __float2half_rn(eWh[(size_t)k * ZZ + n]);
    }
    if (idx < ZZ) g_Bdec[idx] = db[((int)idx & 3) * UU + ((int)idx >> 2)];
    if (idx < BB * UU) {
        int i = (int)idx;
        g_AhH[0][i] = __float2half_rn(0.f);
        g_c[i] = 0.f;
        int b = i >> 9, u = i & 511;
        float s;
        if (u < FF) {
            const float* ip = inputs + (size_t)b * TT * FF + u;
            float acc = 0.f;
            #pragma unroll 4
            for (int t = 0; t < TT; t++) acc += ip[(size_t)t * FF];
            s = acc * (1.0f / TT);
        } else {
            s = score[b];
        }
        g_x0[i] = s;
    }
    if (idx == 0) { g_cnt = 0u; g_gen = 0u; }
}

__global__ void prepX_kernel(const float* __restrict__ inputs, const float* __restrict__ score) {
    size_t idx = (size_t)blockIdx.x * blockDim.x + threadIdx.x;
    if (idx >= (size_t)TT * BB * UU) return;
    int t = (int)(idx / (BB * UU));
    int rem = (int)(idx % (BB * UU));
    int b = rem / UU, u = rem % UU;
    float v = (u < FF) ? inputs[((size_t)b * TT + t) * FF + u] : score[b];
    g_Xt[idx] = tf32r(v);
}

// ---------------- Zx = X @ Wxe + bias : big parallel tf32 GEMM ----------------
__global__ void __launch_bounds__(256) zx_kernel(const float* __restrict__ be) {
    __shared__ float SAx[2][128 * 20];
    __shared__ float SBx[2][16 * 72];
    const int tid = threadIdx.x, lane = tid & 31, wid = tid >> 5;
    const int rowBase = blockIdx.y << 7;
    const int colBase = blockIdx.x << 6;
    const int mB = (wid >> 1) << 5;
    const int nB = (wid & 1) << 5;
    const int gq = lane >> 2, tq = lane & 3;

    const int ar = tid >> 2;
    const int akq = (tid & 3) << 2;
    const int bkr = tid >> 4, bnq = (tid & 15) << 2;
    const float* aptrA = g_Xt + (size_t)(rowBase + ar) * UU + akq;
    const float* aptrB = aptrA + (size_t)64 * UU;
    const float* bptr = g_Wxe + (size_t)bkr * ZZ + colBase + bnq;

    float4 rAa0 = *(const float4*)(aptrA);
    float4 rAb0 = *(const float4*)(aptrB);
    float4 rB0  = *(const float4*)(bptr);
    float4 rAa1 = *(const float4*)(aptrA + 16);
    float4 rAb1 = *(const float4*)(aptrB + 16);
    float4 rB1  = *(const float4*)(bptr + (size_t)16 * ZZ);
    *(float4*)&SAx[0][ar * 20 + akq] = rAa0;
    *(float4*)&SAx[0][(64 + ar) * 20 + akq] = rAb0;
    *(float4*)&SBx[0][bkr * 72 + bnq] = rB0;
    __syncthreads();

    float d[2][4][4];
    #pragma unroll
    for (int i = 0; i < 2; i++)
        #pragma unroll
        for (int j = 0; j < 4; j++)
            #pragma unroll
            for (int q = 0; q < 4; q++) d[i][j][q] = 0.f;

    #pragma unroll 1
    for (int kt = 0; kt < 32; kt += 2) {
        if (kt + 2 < 32) {
            rAa0 = *(const float4*)(aptrA + (kt + 2) * 16);
            rAb0 = *(const float4*)(aptrB + (kt + 2) * 16);
            rB0  = *(const float4*)(bptr + (size_t)(kt + 2) * 16 * ZZ);
        }
        #pragma unroll
        for (int kc = 0; kc < 16; kc += 8) {
            unsigned a0[4], a1[4], bbf[4][2];
            const float* A0 = SAx[0] + (mB + gq) * 20 + kc + tq;
            a0[0] = __float_as_uint(A0[0]);      a0[1] = __float_as_uint(A0[8 * 20]);
            a0[2] = __float_as_uint(A0[4]);      a0[3] = __float_as_uint(A0[8 * 20 + 4]);
            const float* A1 = A0 + 16 * 20;
            a1[0] = __float_as_uint(A1[0]);      a1[1] = __float_as_uint(A1[8 * 20]);
            a1[2] = __float_as_uint(A1[4]);      a1[3] = __float_as_uint(A1[8 * 20 + 4]);
            const float* B0 = SBx[0] + (kc + tq) * 72 + nB + gq;
            #pragma unroll
            for (int ns = 0; ns < 4; ns++) {
                bbf[ns][0] = __float_as_uint(B0[ns * 8]);
                bbf[ns][1] = __float_as_uint(B0[4 * 72 + ns * 8]);
            }
            #pragma unroll
            for (int ns = 0; ns < 4; ns++) { mma_tf32(d[0][ns], a0, bbf[ns]); mma_tf32(d[1][ns], a1, bbf[ns]); }
        }
        *(float4*)&SAx[1][ar * 20 + akq] = rAa1;
        *(float4*)&SAx[1][(64 + ar) * 20 + akq] = rAb1;
        *(float4*)&SBx[1][bkr * 72 + bnq] = rB1;
        __syncthreads();

        if (kt + 3 < 32) {
            rAa1 = *(const float4*)(aptrA + (kt + 3) * 16);
            rAb1 = *(const float4*)(aptrB + (kt + 3) * 16);
            rB1  = *(const float4*)(bptr + (size_t)(kt + 3) * 16 * ZZ);
        }
        #pragma unroll
        for (int kc = 0; kc < 16; kc += 8) {
            unsigned a0[4], a1[4], bbf[4][2];
            const float* A0 = SAx[1] + (mB + gq) * 20 + kc + tq;
            a0[0] = __float_as_uint(A0[0]);      a0[1] = __float_as_uint(A0[8 * 20]);
            a0[2] = __float_as_uint(A0[4]);      a0[3] = __float_as_uint(A0[8 * 20 + 4]);
            const float* A1 = A0 + 16 * 20;
            a1[0] = __float_as_uint(A1[0]);      a1[1] = __float_as_uint(A1[8 * 20]);
            a1[2] = __float_as_uint(A1[4]);      a1[3] = __float_as_uint(A1[8 * 20 + 4]);
            const float* B0 = SBx[1] + (kc + tq) * 72 + nB + gq;
            #pragma unroll
            for (int ns = 0; ns < 4; ns++) {
                bbf[ns][0] = __float_as_uint(B0[ns * 8]);
                bbf[ns][1] = __float_as_uint(B0[4 * 72 + ns * 8]);
            }
            #pragma unroll
            for (int ns = 0; ns < 4; ns++) { mma_tf32(d[0][ns], a0, bbf[ns]); mma_tf32(d[1][ns], a1, bbf[ns]); }
        }
        if (kt + 2 < 32) {
            *(float4*)&SAx[0][ar * 20 + akq] = rAa0;
            *(float4*)&SAx[0][(64 + ar) * 20 + akq] = rAb0;
            *(float4*)&SBx[0][bkr * 72 + bnq] = rB0;
        }
        __syncthreads();
    }

    #pragma unroll
    for (int ms = 0; ms < 2; ms++) {
        #pragma unroll
        for (int ns = 0; ns < 4; ns++) {
            int r0 = rowBase + mB + ms * 16 + gq;
            int c0 = colBase + nB + ns * 8 + 2 * tq;
            int g0 = c0 & 3, u = c0 >> 2;
            float b0 = be[g0 * UU + u], b1 = be[(g0 + 1) * UU + u];
            float2 o1 = { d[ms][ns][0] + b0, d[ms][ns][1] + b1 };
            float2 o2 = { d[ms][ns][2] + b0, d[ms][ns][3] + b1 };
            *(float2*)&g_Zx[(size_t)r0 * ZZ + c0] = o1;
            *(float2*)&g_Zx[(size_t)(r0 + 8) * ZZ + c0] = o2;
        }
    }
}

// ---------------- fp16 W-stationary GEMM mainloop: 16 warps, warp tile 16x16 ----------------
template<int KD>
__device__ __forceinline__ void gemm_f16_loop(const __half* __restrict__ Acta,
                                              const __half* __restrict__ WS,
                                              __half* __restrict__ SA,
                                              float d[2][4]) {
    const int tid = threadIdx.x, lane = tid & 31, wid = tid >> 5;
    const int mB = (wid >> 2) << 4;       // 0,16,32,48
    const int nB = (wid & 3) << 4;        // 0,16,32,48
    const int WSTR = KD + 8;
    const int aRow = (lane & 7) + ((lane >> 3) & 1) * 8;
    const int aK   = (lane >> 4) << 3;
    const int bN   = ((lane >> 4) << 3) + (lane & 7);
    const int bK   = ((lane >> 3) & 1) << 3;

    unsigned saBase = (unsigned)__cvta_generic_to_shared(SA);
    unsigned wsAddr = (unsigned)__cvta_generic_to_shared(WS)
                    + (unsigned)(((nB + bN) * WSTR + bK) * 2);
    unsigned aAddr = saBase + (unsigned)(((mB + aRow) * AST + aK) * 2);

    const bool ldr = tid < 256;
    const int r = tid >> 2, j8 = (tid & 3) << 3;
    const __half* ap = Acta + (size_t)r * KD + j8;

    uint4 p0, p1;
    if (ldr) {
        p0 = *(const uint4*)(ap);
        p1 = *(const uint4*)(ap + 32);
        *(uint4*)&SA[r * AST + j8] = p0;
    }
    __syncthreads();

    constexpr int S = KD / 32;
    #pragma unroll 1
    for (int s = 0; s < S; s++) {
        uint4 nxt;
        if (ldr) {
            if (s + 2 < S) nxt = *(const uint4*)(ap + (s + 2) * 32);
            if (s + 1 < S) *(uint4*)&SA[((s + 1) % 3) * (64 * AST) + r * AST + j8] = p1;
        }
        unsigned sa = aAddr + (unsigned)(((s % 3) * (64 * AST)) * 2);
        unsigned wk = wsAddr + (unsigned)((s << 5) * 2);
        #pragma unroll
        for (int kc = 0; kc < 32; kc += 16) {
            unsigned a0[4], bb[4];
            ldsm_x4(a0[0], a0[1], a0[2], a0[3], sa + kc * 2);
            ldsm_x4(bb[0], bb[1], bb[2], bb[3], wk + kc * 2);
            unsigned b0[2] = { bb[0], bb[1] };
            unsigned b1[2] = { bb[2], bb[3] };
            mma_f16(d[0], a0, b0);
            mma_f16(d[1], a0, b1);
        }
        __syncthreads();
        if (ldr) p1 = nxt;
    }
}

// ---------------- persistent encoder (512 threads) ----------------
#define ENC_WS_H (64 * (UU + 8))
#define ENC_SMEM ((ENC_WS_H + 3 * 64 * AST) * 2)

__global__ void __launch_bounds__(THRP, 1) encoder_kernel() {
    extern __shared__ __half es[];
    __half* WS = es;
    __half* SA = es + ENC_WS_H;

    const int tid = threadIdx.x, lane = tid & 31, wid = tid >> 5;
    const int rowBase = (blockIdx.x >> 5) << 6;
    const int colBase = (blockIdx.x & 31) << 6;
    const int mB = (wid >> 2) << 4;
    const int nB = (wid & 3) << 4;
    const int gq = lane >> 2, tq = lane & 3;

    for (int j = tid; j < 64 * 64; j += THRP) {
        int row = j >> 6, ch = (j & 63) << 3;
        *(uint4*)&WS[row * (UU + 8) + ch] =
            *(const uint4*)&g_WheT[(size_t)(colBase + row) * UU + ch];
    }
    __syncthreads();

    unsigned gen = 0;
    for (int t = 0; t < TT; t++) {
        const __half* Acta = g_AhH[t & 1] + (size_t)rowBase * UU;
        __half* An = g_AhH[(t + 1) & 1];

        float d[2][4];
        #pragma unroll
        for (int j = 0; j < 2; j++)
            #pragma unroll
            for (int q = 0; q < 4; q++) d[j][q] = 0.f;

        gemm_f16_loop<UU>(Acta, WS, SA, d);

        #pragma unroll
        for (int ns = 0; ns < 2; ns++) {
            int r0 = rowBase + mB + gq;
            int c0 = colBase + nB + ns * 8 + 2 * tq;
            const float* zx = &g_Zx[((size_t)t * BB + r0) * ZZ + c0];
            float2 zxa = *(const float2*)zx;
            float2 zxb = *(const float2*)(zx + (size_t)8 * ZZ);
            float z0 = d[ns][0] + zxa.x;
            float z1 = d[ns][1] + zxa.y;
            float z2 = d[ns][2] + zxb.x;
            float z3 = d[ns][3] + zxb.y;
            float p0 = __shfl_xor_sync(0xffffffffu, z0, 1);
            float p1 = __shfl_xor_sync(0xffffffffu, z1, 1);
            float p2 = __shfl_xor_sync(0xffffffffu, z2, 1);
            float p3 = __shfl_xor_sync(0xffffffffu, z3, 1);
            if (!(tq & 1)) {
                int u = c0 >> 2;
                #pragma unroll
                for (int rr = 0; rr < 2; rr++) {
                    int b = r0 + rr * 8;
                    float zi = rr ? z2 : z0, zf = rr ? z3 : z1;
                    float zg = rr ? p2 : p0, zo = rr ? p3 : p1;
                    int idx = b * UU + u;
                    float c = sigf(zf) * g_c[idx] + sigf(zi) * tanhx(zg);
                    float h = sigf(zo) * tanhx(c);
                    g_c[idx] = c;
                    __half hh = __float2half_rn(h);
                    An[idx] = hh;
                    g_encH[((size_t)b * TT + t) * UU + u] = hh;
                }
            }
        }
        gsync(++gen);
    }
}

// ---------------- decoder prologue ----------------
__global__ void decprep_kernel() {
    int idx = blockIdx.x * THR + threadIdx.x;
    if (idx >= BB * UU) return;
    int b = idx >> 9, u = idx & 511;
    g_AdH[0][b * KK + u] = __float2half_rn(g_x0[idx]);
    g_AdH[0][b * KK + UU + u] = g_AhH[0][idx];
}

// ---------------- persistent decoder (512 threads) ----------------
#define DEC_WS_H (64 * (KK + 8))
#define DEC_SA_H (3 * 64 * AST)
#define DEC_SMEM (DEC_WS_H * 2 + DEC_SA_H * 2 + (16 * UU + 2 * TT + 40) * 4)

__global__ void __launch_bounds__(THRP, 1) decoder_kernel(
    const float* __restrict__ ptr_w, const float* __restrict__ ptr_b,
    float* __restrict__ out) {
    extern __shared__ __half ds[];
    __half* WS = ds;
    __half* SA = ds + DEC_WS_H;
    float* wctx = (float*)(ds + DEC_WS_H + DEC_SA_H);   // [16][512]
    float* sc   = wctx + 16 * UU;                       // [2][256]
    float* wm   = sc + 2 * TT;                          // [16]
    float* wz   = wm + 16;                              // [16]

    const int tid = threadIdx.x, lane = tid & 31, warp = tid >> 5;
    const int rowBase = (blockIdx.x >> 5) << 6;
    const int colBase = (blockIdx.x & 31) << 6;
    const int mB = (warp >> 2) << 4;
    const int nB = (warp & 3) << 4;
    const int gq = lane >> 2, tq = lane & 3;

    for (int j = tid; j < 64 * 128; j += THRP) {
        int row = j >> 7, ch = (j & 127) << 3;
        *(uint4*)&WS[row * (KK + 8) + ch] =
            *(const uint4*)&g_WdT[(size_t)(colBase + row) * KK + ch];
    }
    __syncthreads();

    const float w  = *ptr_w;
    const float pb = *ptr_b;
    const int arow = warp >> 3;               // attention row within CTA (0/1)
    const int wr = warp & 7;                  // warp-within-row (8 per row)
    const int batt = blockIdx.x * 2 + arow;

    unsigned gen = TT;
    for (int s = 0; s < TT; s++) {
        const __half* Acta = g_AdH[s & 1] + (size_t)rowBase * KK;
        __half* Anext = g_AdH[(s + 1) & 1];

        float d[2][4];
        #pragma unroll
        for (int j = 0; j < 2; j++)
            #pragma unroll
            for (int q = 0; q < 4; q++) d[j][q] = 0.f;

        gemm_f16_loop<KK>(Acta, WS, SA, d);

        #pragma unroll
        for (int ns = 0; ns < 2; ns++) {
            int c0 = colBase + nB + ns * 8 + 2 * tq;
            float bv0 = g_Bdec[c0], bv1 = g_Bdec[c0 + 1];
            float z0 = d[ns][0] + bv0;
            float z1 = d[ns][1] + bv1;
            float z2 = d[ns][2] + bv0;
            float z3 = d[ns][3] + bv1;
            float p0 = __shfl_xor_sync(0xffffffffu, z0, 1);
            float p1 = __shfl_xor_sync(0xffffffffu, z1, 1);
            float p2 = __shfl_xor_sync(0xffffffffu, z2, 1);
            float p3 = __shfl_xor_sync(0xffffffffu, z3, 1);
            if (!(tq & 1)) {
                int u = c0 >> 2;
                int r0 = rowBase + mB + gq;
                #pragma unroll
                for (int rr = 0; rr < 2; rr++) {
                    int b = r0 + rr * 8;
                    float zi = rr ? z2 : z0, zf = rr ? z3 : z1;
                    float zg = rr ? p2 : p0, zo = rr ? p3 : p1;
                    int idx = b * UU + u;
                    float c = sigf(zf) * g_c[idx] + sigf(zi) * tanhx(zg);
                    float h = sigf(zo) * tanhx(c);
                    g_c[idx] = c;
                    g_h[idx] = h;
                    Anext[b * KK + UU + u] = __float2half_rn(h);
                }
            }
        }
        gsync(++gen);

        // ---- attention: 8 warps/row, 4-way t batching, block-local online softmax ----
        {
            float hx[16];
            {
                const float4* hb = (const float4*)&g_h[batt * UU];
                float4 q0 = hb[2 * lane], q1 = hb[2 * lane + 1];
                float4 q2 = hb[2 * lane + 64], q3 = hb[2 * lane + 65];
                hx[0]=q0.x; hx[1]=q0.y; hx[2]=q0.z; hx[3]=q0.w;
                hx[4]=q1.x; hx[5]=q1.y; hx[6]=q1.z; hx[7]=q1.w;
                hx[8]=q2.x; hx[9]=q2.y; hx[10]=q2.z; hx[11]=q2.w;
                hx[12]=q3.x; hx[13]=q3.y; hx[14]=q3.z; hx[15]=q3.w;
            }
            float ca[16];
            #pragma unroll
            for (int q = 0; q < 16; q++) ca[q] = 0.f;
            float m = -3.0e38f, Zw = 0.f;

            #pragma unroll 1
            for (int it = 0; it < 8; it++) {
                const int t0 = (it << 5) + (wr << 2);
                uint4 E[4][2];
                #pragma unroll
                for (int j = 0; j < 4; j++) {
                    const uint4* ep = (const uint4*)&g_encH[((size_t)batt * TT + t0 + j) * UU];
                    E[j][0] = ep[lane];
                    E[j][1] = ep[lane + 32];
                }
                float sv[4];
                #pragma unroll
                for (int j = 0; j < 4; j++) {
                    float ex[16];
                    cvt16(E[j], ex);
                    float acc = 0.f;
                    #pragma unroll
                    for (int q = 0; q < 16; q++) acc = fmaf(ex[q], hx[q], acc);
                    sv[j] = acc;
                }
                #pragma unroll
                for (int o = 16; o; o >>= 1) {
                    sv[0] += __shfl_xor_sync(0xffffffffu, sv[0], o);
                    sv[1] += __shfl_xor_sync(0xffffffffu, sv[1], o);
                    sv[2] += __shfl_xor_sync(0xffffffffu, sv[2], o);
                    sv[3] += __shfl_xor_sync(0xffffffffu, sv[3], o);
                }
                #pragma unroll
                for (int j = 0; j < 4; j++) sv[j] = sv[j] * w + pb;
                if (lane == 0) {
                    sc[arow * TT + t0 + 0] = sv[0];
                    sc[arow * TT + t0 + 1] = sv[1];
                    sc[arow * TT + t0 + 2] = sv[2];
                    sc[arow * TT + t0 + 3] = sv[3];
                }
                float mloc = fmaxf(fmaxf(sv[0], sv[1]), fmaxf(sv[2], sv[3]));
                float mn = fmaxf(m, mloc);
                float scale = __expf(m - mn);
                float e0 = __expf(sv[0] - mn);
                float e1 = __expf(sv[1] - mn);
                float e2 = __expf(sv[2] - mn);
                float e3 = __expf(sv[3] - mn);
                Zw = Zw * scale + ((e0 + e1) + (e2 + e3));
                float ex[16];
                cvt16(E[0], ex);
                #pragma unroll
                for (int q = 0; q < 16; q++) ca[q] = ca[q] * scale + e0 * ex[q];
                cvt16(E[1], ex);
                #pragma unroll
                for (int q = 0; q < 16; q++) ca[q] = fmaf(e1, ex[q], ca[q]);
                cvt16(E[2], ex);
                #pragma unroll
                for (int q = 0; q < 16; q++) ca[q] = fmaf(e2, ex[q], ca[q]);
                cvt16(E[3], ex);
                #pragma unroll
                for (int q = 0; q < 16; q++) ca[q] = fmaf(e3, ex[q], ca[q]);
                m = mn;
            }
            if (lane == 0) { wm[warp] = m; wz[warp] = Zw; }
            {
                float4* wc = (float4*)&wctx[warp * UU];
                wc[2 * lane]      = make_float4(ca[0], ca[1], ca[2], ca[3]);
                wc[2 * lane + 1]  = make_float4(ca[4], ca[5], ca[6], ca[7]);
                wc[2 * lane + 64] = make_float4(ca[8], ca[9], ca[10], ca[11]);
                wc[2 * lane + 65] = make_float4(ca[12], ca[13], ca[14], ca[15]);
            }
            __syncthreads();

            // combine 8 warps per row; 512 threads -> one u per thread per row
            #pragma unroll
            for (int r = 0; r < 2; r++) {
                int bb = blockIdx.x * 2 + r;
                float M = wm[8 * r];
                #pragma unroll
                for (int q = 1; q < 8; q++) M = fmaxf(M, wm[8 * r + q]);
                float Zt = 0.f, x0a = 0.f;
                #pragma unroll
                for (int q = 0; q < 8; q++) {
                    int qq = 8 * r + q;
                    float e = __expf(wm[qq] - M);
                    Zt += e * wz[qq];
                    x0a += e * wctx[qq * UU + tid];
                }
                float invZ = 1.0f / Zt;
                Anext[bb * KK + tid] = __float2half_rn(x0a * invZ);
                if (tid < TT)
                    out[(size_t)bb * (TT * TT) + (size_t)s * TT + tid] =
                        __expf(sc[r * TT + tid] - M) * invZ;
            }
        }
        gsync(++gen);
    }
}

// ---------------- launch: 6 kernels ----------------
extern "C" void kernel_launch(void* const* d_in, const int* in_sizes, int n_in,
                              void* d_out, int out_size) {
    const float* inputs = (const float*)d_in[0];
    const float* score  = (const float*)d_in[1];
    const float* enc_Wx = (const float*)d_in[2];
    const float* enc_Wh = (const float*)d_in[3];
    const float* enc_b  = (const float*)d_in[4];
    const float* dec_Wx = (const float*)d_in[5];
    const float* dec_Wh = (const float*)d_in[6];
    const float* dec_b  = (const float*)d_in[7];
    const float* ptr_w  = (const float*)d_in[8];
    const float* ptr_b  = (const float*)d_in[9];
    float* out = (float*)d_out;

    cudaFuncSetAttribute(encoder_kernel, cudaFuncAttributeMaxDynamicSharedMemorySize, ENC_SMEM);
    cudaFuncSetAttribute(decoder_kernel, cudaFuncAttributeMaxDynamicSharedMemorySize, DEC_SMEM);

    prepA_kernel<<<(int)(((size_t)KK * ZZ + THR - 1) / THR), THR>>>(
        inputs, score, enc_Wx, enc_Wh, dec_Wx, dec_Wh, dec_b);
    prepX_kernel<<<(int)(((size_t)TT * BB * UU + THR - 1) / THR), THR>>>(inputs, score);

    dim3 zgrid(ZZ / 64, (TT * BB) / 128);
    zx_kernel<<<zgrid, 256>>>(enc_b);

    encoder_kernel<<<GRID, THRP, ENC_SMEM>>>();
    decprep_kernel<<<(BB * UU + THR - 1) / THR, THR>>>();
    decoder_kernel<<<GRID, THRP, DEC_SMEM>>>(ptr_w, ptr_b, out);
}